// round 11
// baseline (speedup 1.0000x reference)
#include <cuda_runtime.h>
#include <cuda_fp16.h>
#include <math.h>
#include <stdint.h>

#define BATCH 32
#define EMB   768
#define HEADS 12
#define HD    64
#define NLAYERS 12
#define NFIX  6
#define NADAPT 6
#define MLPD  3072
#define NCLS  100
#define NTOK  198
#define NT2   197
#define RPAD  256              // padded rows per sample in adaptive phase
#define MAXR  (BATCH*RPAD)     // 8192 rows
#define PE_NN 100
#define PE_DD 256
#define NPATCH 196

// ---------------- scratch (device globals; no allocation allowed) ------------
__device__ float g_tok [BATCH*NTOK*EMB];
__device__ __align__(16) __half g_xn  [MAXR*EMB];
__device__ __align__(16) __half g_qkv [MAXR*3*EMB];
__device__ __align__(16) __half g_attb[MAXR*EMB];
__device__ __align__(16) __half g_mlpb[MAXR*MLPD];
__device__ float g_t   [MAXR*EMB];
__device__ float g_t2  [MAXR*EMB];
__device__ __align__(16) __half g_col [BATCH*NPATCH*EMB];
__device__ float g_pat [BATCH*NPATCH*EMB];
__device__ float g_lat1[BATCH*EMB];
__device__ __align__(16) __half g_lat2[BATCH*EMB];
__device__ float g_lat3[BATCH*EMB];
__device__ __align__(16) __half g_cls [BATCH*EMB];
__device__ int   g_actv[BATCH*NADAPT];
__device__ __align__(16) __half g_wqkv [NLAYERS*3*EMB*EMB];
__device__ __align__(16) __half g_wproj[NLAYERS*EMB*EMB];
__device__ __align__(16) __half g_wfc1 [NLAYERS*MLPD*EMB];
__device__ __align__(16) __half g_wfc2 [NLAYERS*EMB*MLPD];
__device__ __align__(16) __half g_wlat2[EMB*EMB];
__device__ __align__(16) __half g_wpat [EMB*EMB];

__device__ __forceinline__ float gelu_f(float v) {
    return 0.5f * v * (1.0f + erff(v * 0.70710678118654752440f));
}
__device__ __forceinline__ uint32_t smem_u32(const void* p) {
    uint32_t a;
    asm("{ .reg .u64 t; cvta.to.shared.u64 t, %1; cvt.u32.u64 %0, t; }" : "=r"(a) : "l"(p));
    return a;
}
__device__ __forceinline__ uint32_t h2_u32(__half2 h) {
    uint32_t u;
    *(__half2*)&u = h;
    return u;
}
__device__ __forceinline__ void cp16(uint32_t dst, const void* src, bool pred) {
    int sz = pred ? 16 : 0;
    asm volatile("cp.async.cg.shared.global [%0], [%1], 16, %2;"
                 :: "r"(dst), "l"(src), "r"(sz) : "memory");
}
__device__ __forceinline__ void mma_f16(float c[4], const uint32_t a[4], const uint32_t b[2]) {
    asm volatile(
        "mma.sync.aligned.m16n8k16.row.col.f32.f16.f16.f32 "
        "{%0,%1,%2,%3}, {%4,%5,%6,%7}, {%8,%9}, {%0,%1,%2,%3};\n"
        : "+f"(c[0]), "+f"(c[1]), "+f"(c[2]), "+f"(c[3])
        : "r"(a[0]), "r"(a[1]), "r"(a[2]), "r"(a[3]), "r"(b[0]), "r"(b[1]));
}
__device__ __forceinline__ void ldsm_x4(uint32_t r[4], uint32_t addr) {
    asm volatile("ldmatrix.sync.aligned.m8n8.x4.shared.b16 {%0,%1,%2,%3}, [%4];"
                 : "=r"(r[0]), "=r"(r[1]), "=r"(r[2]), "=r"(r[3]) : "r"(addr));
}

// ---------------- fp16 tensor-core GEMM: C = A[M,K] @ Bt[N,K]^T -------------
// 128x128x64 tiles, 3-stage cp.async pipeline, ldmatrix fragment loads.
// gate: per-sample active flags; gate_rows also gates epilogue row writes.
#define HST2 72                               // halves per smem row (144 B)
#define GSTAGE (128 * HST2)                   // halves per stage per operand
#define GEMM_SMEM_BYTES (6 * GSTAGE * 2)      // 110592 (3 stages x A,B)
template<int ACT, bool RES, bool OUTH>
__global__ void __launch_bounds__(256) hgemm_k(
    const __half* __restrict__ A, const __half* __restrict__ Bt,
    const float* __restrict__ bias, const float* __restrict__ res,
    float* __restrict__ Cf, __half* __restrict__ Ch, int M, int N, int K,
    const int* __restrict__ gate, int gstride, int rps, int gate_rows)
{
    const int brow = blockIdx.y * 128;
    if (gate) {
        const int s0 = brow / rps;
        const int s1 = min(brow + 127, M - 1) / rps;
        bool any = false;
        for (int s = s0; s <= s1; s++) any |= (gate[s * gstride] != 0);
        if (!any) return;
    }

    extern __shared__ __align__(16) __half hsm[];
    const uint32_t saU[3] = { smem_u32(hsm),
                              smem_u32(hsm + 2 * GSTAGE),
                              smem_u32(hsm + 4 * GSTAGE) };
    const uint32_t sbU[3] = { smem_u32(hsm + GSTAGE),
                              smem_u32(hsm + 3 * GSTAGE),
                              smem_u32(hsm + 5 * GSTAGE) };

    const int tid  = threadIdx.x;
    const int warp = tid >> 5, lane = tid & 31;
    const int bcol = blockIdx.x * 128;
    const int warpM = (warp >> 2) * 64;
    const int warpN = (warp & 3) * 32;
    const int g4 = lane >> 2, l2 = (lane & 3) * 2;

    // per-lane ldmatrix row/col offset (halves)
    const int lmoff = ((lane & 7) + ((lane >> 3) & 1) * 8) * HST2 + (lane >> 4) * 8;

    float acc[4][4][4];
    #pragma unroll
    for (int i = 0; i < 4; i++)
        #pragma unroll
        for (int j = 0; j < 4; j++)
            #pragma unroll
            for (int r = 0; r < 4; r++) acc[i][j][r] = 0.0f;

    const int nch = K >> 6;                   // 64-K chunks

    auto LOAD = [&](int chunk, int st) {
        const int k0 = chunk << 6;
        const uint32_t da = saU[st], db = sbU[st];
        #pragma unroll
        for (int i = 0; i < 4; i++) {
            const int ch  = i * 256 + tid;    // 0..1023
            const int row = ch >> 3, col = ch & 7;
            cp16(da + row * (HST2 * 2) + col * 16,
                 A + (size_t)(brow + row) * K + k0 + col * 8, (brow + row) < M);
            cp16(db + row * (HST2 * 2) + col * 16,
                 Bt + (size_t)(bcol + row) * K + k0 + col * 8, true);
        }
        asm volatile("cp.async.commit_group;" ::: "memory");
    };

    LOAD(0, 0);
    if (nch > 1) LOAD(1, 1);

    for (int c = 0; c < nch; c++) {
        const int st = c % 3;
        if (c + 2 < nch) {
            LOAD(c + 2, (c + 2) % 3);
            asm volatile("cp.async.wait_group 2;" ::: "memory");
        } else if (c + 1 < nch) {
            asm volatile("cp.async.wait_group 1;" ::: "memory");
        } else {
            asm volatile("cp.async.wait_group 0;" ::: "memory");
        }
        __syncthreads();

        const uint32_t aB = saU[st], bB = sbU[st];
        #pragma unroll
        for (int ks = 0; ks < 4; ks++) {
            uint32_t af[4][4], bf[4][2];
            #pragma unroll
            for (int tm = 0; tm < 4; tm++)
                ldsm_x4(af[tm], aB + 2 * ((warpM + tm * 16) * HST2 + ks * 16 + lmoff));
            #pragma unroll
            for (int tnp = 0; tnp < 2; tnp++) {
                uint32_t rb[4];
                ldsm_x4(rb, bB + 2 * ((warpN + tnp * 16) * HST2 + ks * 16 + lmoff));
                bf[2 * tnp][0]     = rb[0];
                bf[2 * tnp + 1][0] = rb[1];
                bf[2 * tnp][1]     = rb[2];
                bf[2 * tnp + 1][1] = rb[3];
            }
            #pragma unroll
            for (int tm = 0; tm < 4; tm++)
                #pragma unroll
                for (int tn = 0; tn < 4; tn++)
                    mma_f16(acc[tm][tn], af[tm], bf[tn]);
        }
        __syncthreads();
    }

    #pragma unroll
    for (int tm = 0; tm < 4; tm++) {
        const int rr = brow + warpM + tm * 16 + g4;
        #pragma unroll
        for (int half = 0; half < 2; half++) {
            const int gr = rr + half * 8;
            if (gr >= M) continue;
            if (gate_rows && gate && !gate[(gr / rps) * gstride]) continue;
            #pragma unroll
            for (int tn = 0; tn < 4; tn++) {
                const int gc = bcol + warpN + tn * 8 + l2;
                float o0 = acc[tm][tn][half * 2 + 0] + bias[gc];
                float o1 = acc[tm][tn][half * 2 + 1] + bias[gc + 1];
                if (ACT == 1) { o0 = gelu_f(o0); o1 = gelu_f(o1); }
                if (RES) {
                    o0 += res[(size_t)gr * N + gc];
                    o1 += res[(size_t)gr * N + gc + 1];
                }
                if (OUTH) {
                    *(__half2*)&Ch[(size_t)gr * N + gc] = __floats2half2_rn(o0, o1);
                } else {
                    Cf[(size_t)gr * N + gc]     = o0;
                    Cf[(size_t)gr * N + gc + 1] = o1;
                }
            }
        }
    }
}

// ---------------- weight transpose+convert ----------------------------------
__global__ void transpose_k(const float* __restrict__ in, __half* __restrict__ out,
                            int K, int N)
{
    __shared__ float t[32][33];
    const int l = blockIdx.z;
    const float* ip = in  + (size_t)l * K * N;
    __half*      op = out + (size_t)l * K * N;
    const int k0 = blockIdx.y * 32, n0 = blockIdx.x * 32;
    #pragma unroll
    for (int i = 0; i < 32; i += 8) {
        int k = k0 + threadIdx.y + i, n = n0 + threadIdx.x;
        if (k < K && n < N) t[threadIdx.y + i][threadIdx.x] = ip[(size_t)k * N + n];
    }
    __syncthreads();
    #pragma unroll
    for (int i = 0; i < 32; i += 8) {
        int n = n0 + threadIdx.y + i, k = k0 + threadIdx.x;
        if (n < N && k < K) op[(size_t)n * K + k] = __float2half_rn(t[threadIdx.x][threadIdx.y + i]);
    }
}

__global__ void cvt_k(const float* __restrict__ in, __half* __restrict__ out, long n)
{
    long i = (long)blockIdx.x * blockDim.x + threadIdx.x;
    if (i < n) out[i] = __float2half_rn(in[i]);
}

// ---------------- LayerNorm over 768 (fp32 in, half out), gated -------------
// vr: valid rows per sample (rows with row%rps >= vr are skipped).
__global__ void __launch_bounds__(192) ln_k(
    const float* __restrict__ X, long istride,
    const float* __restrict__ g, const float* __restrict__ b,
    __half* __restrict__ Y, long ostride,
    const int* __restrict__ gate, int gstride, int rps, int vr)
{
    const int row = blockIdx.x;
    const int smp = row / rps;
    if ((row - smp * rps) >= vr) return;
    if (gate && !gate[smp * gstride]) return;
    const int tid = threadIdx.x;
    const float* x = X + (size_t)row * istride;
    __half* y      = Y + (size_t)row * ostride;
    __shared__ float red[6];
    __shared__ float stat[2];

    const float4 v = *(const float4*)&x[tid * 4];
    float s = v.x + v.y + v.z + v.w;
    #pragma unroll
    for (int o = 16; o; o >>= 1) s += __shfl_xor_sync(~0u, s, o);
    if ((tid & 31) == 0) red[tid >> 5] = s;
    __syncthreads();
    if (tid == 0) {
        float t = 0.f;
        #pragma unroll
        for (int i = 0; i < 6; i++) t += red[i];
        stat[0] = t * (1.0f / 768.0f);
    }
    __syncthreads();
    const float mean = stat[0];
    const float d0 = v.x - mean, d1 = v.y - mean, d2 = v.z - mean, d3 = v.w - mean;
    s = d0 * d0 + d1 * d1 + d2 * d2 + d3 * d3;
    #pragma unroll
    for (int o = 16; o; o >>= 1) s += __shfl_xor_sync(~0u, s, o);
    __syncthreads();
    if ((tid & 31) == 0) red[tid >> 5] = s;
    __syncthreads();
    if (tid == 0) {
        float t = 0.f;
        #pragma unroll
        for (int i = 0; i < 6; i++) t += red[i];
        stat[1] = rsqrtf(t * (1.0f / 768.0f) + 1e-5f);
    }
    __syncthreads();
    const float rstd = stat[1];
    const float4 gv = *(const float4*)&g[tid * 4];
    const float4 bv = *(const float4*)&b[tid * 4];
    __half2 h01 = __floats2half2_rn(d0 * rstd * gv.x + bv.x, d1 * rstd * gv.y + bv.y);
    __half2 h23 = __floats2half2_rn(d2 * rstd * gv.z + bv.z, d3 * rstd * gv.w + bv.w);
    *(__half2*)&y[tid * 4]     = h01;
    *(__half2*)&y[tid * 4 + 2] = h23;
}

// ---------------- tensor-core attention: one CTA (128 thr) per (b,h) --------
// rowstride: rows per sample in the qkv / O buffers. N: valid tokens.
#define APAD 208
#define KST  72
#define VST  216
#define ATTN_SMEM_BYTES ((2*APAD*KST + 64*VST) * 2)

__global__ void __launch_bounds__(128) attn_k(const __half* __restrict__ qkv,
                                              __half* __restrict__ O, int N, int rowstride,
                                              const int* __restrict__ gate, int gstride)
{
    const int bh = blockIdx.x;
    const int b  = bh / HEADS, h = bh % HEADS;
    if (gate && !gate[b * gstride]) return;

    extern __shared__ __half smh[];
    __half* Qs = smh;
    __half* Ks = Qs + APAD * KST;
    __half* Vt = Ks + APAD * KST;

    const int tid = threadIdx.x;
    const int w = tid >> 5, lane = tid & 31;
    const int g4 = lane >> 2, l2 = (lane & 3) * 2;
    const __half* base = qkv + (size_t)b * rowstride * (3 * EMB) + h * 64;

    for (int n = tid; n < APAD; n += 128) {
        uint4* qd = (uint4*)&Qs[n * KST];
        uint4* kd = (uint4*)&Ks[n * KST];
        if (n < N) {
            const uint4* qs = (const uint4*)(base + (size_t)n * (3 * EMB));
            const uint4* ks = (const uint4*)(base + (size_t)n * (3 * EMB) + EMB);
            #pragma unroll
            for (int i = 0; i < 8; i++) { qd[i] = qs[i]; kd[i] = ks[i]; }
        } else {
            uint4 z = make_uint4(0, 0, 0, 0);
            #pragma unroll
            for (int i = 0; i < 8; i++) { qd[i] = z; kd[i] = z; }
        }
    }
    for (int idx = tid; idx < APAD * 64; idx += 128) {
        const int n = idx >> 6, d = idx & 63;
        __half v = (n < N) ? base[(size_t)n * (3 * EMB) + 2 * EMB + d] : __ushort_as_half(0);
        Vt[d * VST + n] = v;
    }
    __syncthreads();

    for (int qt = w; qt < 13; qt += 4) {
        const int q0 = qt * 16;
        uint32_t aq[4][4];
        #pragma unroll
        for (int ks = 0; ks < 4; ks++) {
            const int kk = ks * 16 + l2;
            aq[ks][0] = *(const uint32_t*)&Qs[(q0 + g4) * KST + kk];
            aq[ks][1] = *(const uint32_t*)&Qs[(q0 + g4 + 8) * KST + kk];
            aq[ks][2] = *(const uint32_t*)&Qs[(q0 + g4) * KST + kk + 8];
            aq[ks][3] = *(const uint32_t*)&Qs[(q0 + g4 + 8) * KST + kk + 8];
        }
        float sc[26][4];
        #pragma unroll
        for (int nt = 0; nt < 26; nt++) {
            sc[nt][0] = sc[nt][1] = sc[nt][2] = sc[nt][3] = 0.f;
            #pragma unroll
            for (int ks = 0; ks < 4; ks++) {
                const int kk = ks * 16 + l2;
                uint32_t bf[2];
                bf[0] = *(const uint32_t*)&Ks[(nt * 8 + g4) * KST + kk];
                bf[1] = *(const uint32_t*)&Ks[(nt * 8 + g4) * KST + kk + 8];
                mma_f16(sc[nt], aq[ks], bf);
            }
        }
        float m0 = -1e30f, m1 = -1e30f;
        #pragma unroll
        for (int nt = 0; nt < 26; nt++) {
            #pragma unroll
            for (int e = 0; e < 2; e++) {
                const int col = nt * 8 + l2 + e;
                const bool ok = col < N;
                float v0 = ok ? sc[nt][e]     * 0.125f : -1e30f;
                float v1 = ok ? sc[nt][2 + e] * 0.125f : -1e30f;
                sc[nt][e] = v0; sc[nt][2 + e] = v1;
                m0 = fmaxf(m0, v0); m1 = fmaxf(m1, v1);
            }
        }
        m0 = fmaxf(m0, __shfl_xor_sync(~0u, m0, 1));
        m0 = fmaxf(m0, __shfl_xor_sync(~0u, m0, 2));
        m1 = fmaxf(m1, __shfl_xor_sync(~0u, m1, 1));
        m1 = fmaxf(m1, __shfl_xor_sync(~0u, m1, 2));
        float s0 = 0.f, s1 = 0.f;
        #pragma unroll
        for (int nt = 0; nt < 26; nt++) {
            #pragma unroll
            for (int e = 0; e < 2; e++) {
                float e0 = __expf(sc[nt][e]     - m0);
                float e1 = __expf(sc[nt][2 + e] - m1);
                sc[nt][e] = e0; sc[nt][2 + e] = e1;
                s0 += e0; s1 += e1;
            }
        }
        s0 += __shfl_xor_sync(~0u, s0, 1); s0 += __shfl_xor_sync(~0u, s0, 2);
        s1 += __shfl_xor_sync(~0u, s1, 1); s1 += __shfl_xor_sync(~0u, s1, 2);
        const float i0 = 1.0f / s0, i1 = 1.0f / s1;
        float o[8][4];
        #pragma unroll
        for (int dt = 0; dt < 8; dt++) o[dt][0] = o[dt][1] = o[dt][2] = o[dt][3] = 0.f;
        #pragma unroll
        for (int kt = 0; kt < 13; kt++) {
            uint32_t ap[4];
            ap[0] = h2_u32(__floats2half2_rn(sc[2*kt][0]   * i0, sc[2*kt][1]   * i0));
            ap[1] = h2_u32(__floats2half2_rn(sc[2*kt][2]   * i1, sc[2*kt][3]   * i1));
            ap[2] = h2_u32(__floats2half2_rn(sc[2*kt+1][0] * i0, sc[2*kt+1][1] * i0));
            ap[3] = h2_u32(__floats2half2_rn(sc[2*kt+1][2] * i1, sc[2*kt+1][3] * i1));
            #pragma unroll
            for (int dt = 0; dt < 8; dt++) {
                uint32_t bv[2];
                bv[0] = *(const uint32_t*)&Vt[(dt * 8 + g4) * VST + kt * 16 + l2];
                bv[1] = *(const uint32_t*)&Vt[(dt * 8 + g4) * VST + kt * 16 + l2 + 8];
                mma_f16(o[dt], ap, bv);
            }
        }
        const int r0 = q0 + g4, r1 = q0 + g4 + 8;
        __half* ob = O + (size_t)b * rowstride * EMB + h * 64;
        #pragma unroll
        for (int dt = 0; dt < 8; dt++) {
            const int c = dt * 8 + l2;
            if (r0 < N)
                *(__half2*)&ob[(size_t)r0 * EMB + c] = __floats2half2_rn(o[dt][0], o[dt][1]);
            if (r1 < N)
                *(__half2*)&ob[(size_t)r1 * EMB + c] = __floats2half2_rn(o[dt][2], o[dt][3]);
        }
    }
}

// ---------------- small / elementwise kernels -------------------------------
__global__ void im2col_k(const float* __restrict__ x, __half* __restrict__ col, long total)
{
    long i = (long)blockIdx.x * blockDim.x + threadIdx.x;
    if (i >= total) return;
    int k = (int)(i % EMB);
    long m = i / EMB;
    int b = (int)(m / NPATCH), p = (int)(m % NPATCH);
    int c = k >> 8, r = k & 255, ii = r >> 4, jj = r & 15;
    int py = p / 14, px = p % 14;
    col[i] = __float2half_rn(x[(((size_t)b * 3 + c) * 224 + py * 16 + ii) * 224 + px * 16 + jj]);
}

__global__ void lat1_k(const float* __restrict__ pe, const float* __restrict__ w1,
                       const float* __restrict__ b1, const float* __restrict__ budget,
                       float* __restrict__ out)
{
    int b = blockIdx.x;
    int idx = (int)rintf(budget[b] * (float)(PE_NN - 1));
    const float* row = pe + (size_t)idx * PE_DD;
    for (int e = threadIdx.x; e < EMB; e += 256) {
        float s = b1[e];
        for (int k = 0; k < PE_DD; k++) s += row[k] * w1[(size_t)k * EMB + e];
        out[(size_t)b * EMB + e] = gelu_f(s);
    }
}

__global__ void assemble_k(const float* __restrict__ lat, const float* __restrict__ cls,
                           const float* __restrict__ pat, const float* __restrict__ pos,
                           float* __restrict__ tok, long total)
{
    long i = (long)blockIdx.x * blockDim.x + threadIdx.x;
    if (i >= total) return;
    int e = (int)(i % EMB);
    long bn = i / EMB;
    int n = (int)(bn % NTOK), b = (int)(bn / NTOK);
    float v;
    if (n == 0)      v = lat[(size_t)b * EMB + e];
    else if (n == 1) v = cls[e];
    else             v = pat[((size_t)b * NPATCH + (n - 2)) * EMB + e];
    tok[i] = v + pos[(size_t)n * EMB + e];
}

__global__ void sched_k(const float* __restrict__ tok, const float* __restrict__ sw,
                        const float* __restrict__ sb, const float* __restrict__ budget,
                        int* __restrict__ active)
{
    int b = blockIdx.x, lane = threadIdx.x;
    __shared__ float lg[NADAPT];
    if (lane < NADAPT) {
        const float* x = tok + (size_t)b * NTOK * EMB;
        float s = sb[lane];
        for (int k = 0; k < EMB; k++) s += x[k] * sw[(size_t)k * NADAPT + lane];
        lg[lane] = s;
    }
    __syncwarp();
    if (lane < NADAPT) {
        int kk = (int)ceilf(budget[b] * (float)NADAPT);
        if (kk < 1) kk = 1;
        int rank = 0;
        for (int j = 0; j < NADAPT; j++)
            if (lg[j] > lg[lane] || (lg[j] == lg[lane] && j < lane)) rank++;
        active[b * NADAPT + lane] = (rank < kk) ? 1 : 0;
    }
}

// extract tokens 1..197 of each sample into padded layout (RPAD rows/sample)
__global__ void extract_k(const float* __restrict__ tok, float* __restrict__ t, long total)
{
    long i = (long)blockIdx.x * blockDim.x + threadIdx.x;
    if (i >= total) return;
    int e = (int)(i % EMB);
    long bn = i / EMB;
    int n = (int)(bn % NT2), b = (int)(bn / NT2);
    t[((size_t)b * RPAD + n) * EMB + e] = tok[((size_t)b * NTOK + n + 1) * EMB + e];
}

__global__ void head_k(const __half* __restrict__ cls, const float* __restrict__ w,
                       const float* __restrict__ bias, float* __restrict__ out)
{
    int b = blockIdx.x, c = threadIdx.x;
    if (c >= NCLS) return;
    const __half* x = cls + (size_t)b * EMB;
    float s = bias[c];
    for (int k = 0; k < EMB; k++) s += __half2float(x[k]) * w[(size_t)k * NCLS + c];
    out[(size_t)b * NCLS + c] = s;
}

// ---------------- host orchestration ----------------------------------------
static inline void launch_gemm(int act, bool res, bool outh,
                               const __half* A, const __half* Bt, const float* bias,
                               const float* r, float* Cf, __half* Ch, int M, int N, int K,
                               const int* gate, int gstride, int rps, int gate_rows)
{
    dim3 g(N / 128, (M + 127) / 128), blk(256);
    if (outh) {
        if (act == 1)      hgemm_k<1, false, true><<<g, blk, GEMM_SMEM_BYTES>>>(A, Bt, bias, r, Cf, Ch, M, N, K, gate, gstride, rps, gate_rows);
        else               hgemm_k<0, false, true><<<g, blk, GEMM_SMEM_BYTES>>>(A, Bt, bias, r, Cf, Ch, M, N, K, gate, gstride, rps, gate_rows);
    } else {
        if (res)           hgemm_k<0, true,  false><<<g, blk, GEMM_SMEM_BYTES>>>(A, Bt, bias, r, Cf, Ch, M, N, K, gate, gstride, rps, gate_rows);
        else               hgemm_k<0, false, false><<<g, blk, GEMM_SMEM_BYTES>>>(A, Bt, bias, r, Cf, Ch, M, N, K, gate, gstride, rps, gate_rows);
    }
}

struct Ptrs {
    float *tok, *t, *t2, *pat, *lat1, *lat3;
    __half *xn, *qkv, *att, *mlp, *col, *lat2, *cls;
    __half *wqkv, *wproj, *wfc1, *wfc2, *wlat2, *wpat;
    int   *actv;
};

// rps: rows per sample (incl. padding), vr: valid rows per sample.
static void run_block(const Ptrs& P, float* Xin, float* Xmid, float* Xout,
                      int rps, int vr, int l,
                      const float* ln1g, const float* ln1b, const float* qkvb,
                      const float* projb, const float* ln2g, const float* ln2b,
                      const float* fc1b, const float* fc2b,
                      const int* gate, int gstride, int gate_rows)
{
    const int M = BATCH * rps;
    ln_k<<<M, 192>>>(Xin, EMB, ln1g + (size_t)l * EMB, ln1b + (size_t)l * EMB,
                     P.xn, EMB, gate, gstride, rps, vr);
    launch_gemm(0, false, true, P.xn, P.wqkv + (size_t)l * EMB * 3 * EMB,
                qkvb + (size_t)l * 3 * EMB, nullptr, nullptr, P.qkv, M, 3 * EMB, EMB,
                gate, gstride, rps, 0);
    attn_k<<<BATCH * HEADS, 128, ATTN_SMEM_BYTES>>>(P.qkv, P.att, vr, rps, gate, gstride);
    launch_gemm(0, true, false, P.att, P.wproj + (size_t)l * EMB * EMB,
                projb + (size_t)l * EMB, Xin, Xmid, nullptr, M, EMB, EMB,
                gate, gstride, rps, 0);
    ln_k<<<M, 192>>>(Xmid, EMB, ln2g + (size_t)l * EMB, ln2b + (size_t)l * EMB,
                     P.xn, EMB, gate, gstride, rps, vr);
    launch_gemm(1, false, true, P.xn, P.wfc1 + (size_t)l * EMB * MLPD,
                fc1b + (size_t)l * MLPD, nullptr, nullptr, P.mlp, M, MLPD, EMB,
                gate, gstride, rps, 0);
    launch_gemm(0, true, false, P.mlp, P.wfc2 + (size_t)l * MLPD * EMB,
                fc2b + (size_t)l * EMB, Xmid, Xout, nullptr, M, EMB, MLPD,
                gate, gstride, rps, gate_rows);
}

extern "C" void kernel_launch(void* const* d_in, const int* in_sizes, int n_in,
                              void* d_out, int out_size)
{
    const float* x        = (const float*)d_in[0];
    const float* budget   = (const float*)d_in[1];
    const float* pe_table = (const float*)d_in[2];
    const float* lat_w1   = (const float*)d_in[3];
    const float* lat_b1   = (const float*)d_in[4];
    const float* lat_ln_g = (const float*)d_in[5];
    const float* lat_ln_b = (const float*)d_in[6];
    const float* lat_w2   = (const float*)d_in[7];
    const float* lat_b2   = (const float*)d_in[8];
    const float* patch_w  = (const float*)d_in[9];
    const float* patch_b  = (const float*)d_in[10];
    const float* cls_tok  = (const float*)d_in[11];
    const float* pos_emb  = (const float*)d_in[12];
    const float* sched_w  = (const float*)d_in[13];
    const float* sched_b  = (const float*)d_in[14];
    const float* ln1_g    = (const float*)d_in[15];
    const float* ln1_b    = (const float*)d_in[16];
    const float* qkv_w    = (const float*)d_in[17];
    const float* qkv_b    = (const float*)d_in[18];
    const float* proj_w   = (const float*)d_in[19];
    const float* proj_b   = (const float*)d_in[20];
    const float* ln2_g    = (const float*)d_in[21];
    const float* ln2_b    = (const float*)d_in[22];
    const float* fc1_w    = (const float*)d_in[23];
    const float* fc1_b    = (const float*)d_in[24];
    const float* fc2_w    = (const float*)d_in[25];
    const float* fc2_b    = (const float*)d_in[26];
    const float* norm_g   = (const float*)d_in[27];
    const float* norm_b   = (const float*)d_in[28];
    const float* head_w   = (const float*)d_in[29];
    const float* head_b   = (const float*)d_in[30];
    float* out = (float*)d_out;

    Ptrs P;
    cudaGetSymbolAddress((void**)&P.tok,  g_tok);
    cudaGetSymbolAddress((void**)&P.xn,   g_xn);
    cudaGetSymbolAddress((void**)&P.qkv,  g_qkv);
    cudaGetSymbolAddress((void**)&P.att,  g_attb);
    cudaGetSymbolAddress((void**)&P.mlp,  g_mlpb);
    cudaGetSymbolAddress((void**)&P.t,    g_t);
    cudaGetSymbolAddress((void**)&P.t2,   g_t2);
    cudaGetSymbolAddress((void**)&P.col,  g_col);
    cudaGetSymbolAddress((void**)&P.pat,  g_pat);
    cudaGetSymbolAddress((void**)&P.lat1, g_lat1);
    cudaGetSymbolAddress((void**)&P.lat2, g_lat2);
    cudaGetSymbolAddress((void**)&P.lat3, g_lat3);
    cudaGetSymbolAddress((void**)&P.cls,  g_cls);
    cudaGetSymbolAddress((void**)&P.actv, g_actv);
    cudaGetSymbolAddress((void**)&P.wqkv, g_wqkv);
    cudaGetSymbolAddress((void**)&P.wproj,g_wproj);
    cudaGetSymbolAddress((void**)&P.wfc1, g_wfc1);
    cudaGetSymbolAddress((void**)&P.wfc2, g_wfc2);
    cudaGetSymbolAddress((void**)&P.wlat2,g_wlat2);
    cudaGetSymbolAddress((void**)&P.wpat, g_wpat);

    cudaFuncSetAttribute(attn_k, cudaFuncAttributeMaxDynamicSharedMemorySize, ATTN_SMEM_BYTES);
    cudaFuncSetAttribute(hgemm_k<0,false,true >, cudaFuncAttributeMaxDynamicSharedMemorySize, GEMM_SMEM_BYTES);
    cudaFuncSetAttribute(hgemm_k<1,false,true >, cudaFuncAttributeMaxDynamicSharedMemorySize, GEMM_SMEM_BYTES);
    cudaFuncSetAttribute(hgemm_k<0,true, false>, cudaFuncAttributeMaxDynamicSharedMemorySize, GEMM_SMEM_BYTES);
    cudaFuncSetAttribute(hgemm_k<0,false,false>, cudaFuncAttributeMaxDynamicSharedMemorySize, GEMM_SMEM_BYTES);

    // --- weight transposes+convert ([K,N] fp32 -> [N,K] half) ---
    {
        dim3 b32(32, 8);
        transpose_k<<<dim3(3*EMB/32, EMB/32, NLAYERS), b32>>>(qkv_w,  P.wqkv,  EMB, 3*EMB);
        transpose_k<<<dim3(EMB/32,   EMB/32, NLAYERS), b32>>>(proj_w, P.wproj, EMB, EMB);
        transpose_k<<<dim3(MLPD/32,  EMB/32, NLAYERS), b32>>>(fc1_w,  P.wfc1,  EMB, MLPD);
        transpose_k<<<dim3(EMB/32,  MLPD/32, NLAYERS), b32>>>(fc2_w,  P.wfc2,  MLPD, EMB);
        transpose_k<<<dim3(EMB/32,   EMB/32, 1),       b32>>>(lat_w2, P.wlat2, EMB, EMB);
        long pw = (long)EMB * EMB;
        cvt_k<<<(unsigned)((pw + 255) / 256), 256>>>(patch_w, P.wpat, pw);
    }

    // --- latent token ---
    lat1_k<<<BATCH, 256>>>(pe_table, lat_w1, lat_b1, budget, P.lat1);
    ln_k<<<BATCH, 192>>>(P.lat1, EMB, lat_ln_g, lat_ln_b, P.lat2, EMB, nullptr, 0, 1, 1);
    launch_gemm(0, false, false, P.lat2, P.wlat2, lat_b2, nullptr, P.lat3, nullptr,
                BATCH, EMB, EMB, nullptr, 0, 1, 0);

    // --- patch embedding ---
    {
        long tot = (long)BATCH * NPATCH * EMB;
        im2col_k<<<(unsigned)((tot + 255) / 256), 256>>>(x, P.col, tot);
        launch_gemm(0, false, false, P.col, P.wpat, patch_b, nullptr, P.pat, nullptr,
                    BATCH * NPATCH, EMB, EMB, nullptr, 0, 1, 0);
        long ta = (long)BATCH * NTOK * EMB;
        assemble_k<<<(unsigned)((ta + 255) / 256), 256>>>(P.lat3, cls_tok, P.pat,
                                                          pos_emb, P.tok, ta);
    }

    // --- 6 fixed blocks on 198 tokens (contiguous layout, in-place on tok) ---
    for (int l = 0; l < NFIX; l++)
        run_block(P, P.tok, P.tok, P.tok, NTOK, NTOK, l, ln1_g, ln1_b, qkv_b, proj_b,
                  ln2_g, ln2_b, fc1_b, fc2_b, nullptr, 0, 0);

    // --- scheduler gating ---
    sched_k<<<BATCH, 32>>>(P.tok, sched_w, sched_b, budget, P.actv);

    // --- adaptive blocks on 197 tokens, RPAD-padded layout for exact tile gating
    const long tlen = (long)BATCH * NT2 * EMB;
    extract_k<<<(unsigned)((tlen + 255) / 256), 256>>>(P.tok, P.t, tlen);
    for (int i = 0; i < NADAPT; i++) {
        const int* gate = P.actv + i;    // gate[s * NADAPT] = active[s][i]
        run_block(P, P.t, P.t2, P.t, RPAD, NT2, NFIX + i, ln1_g, ln1_b, qkv_b, proj_b,
                  ln2_g, ln2_b, fc1_b, fc2_b, gate, NADAPT, 1);
    }

    // --- final LN on token 0 of each sample (padded stride) + head ---
    ln_k<<<BATCH, 192>>>(P.t, (long)RPAD * EMB, norm_g, norm_b, P.cls, EMB,
                         nullptr, 0, 1, 1);
    head_k<<<BATCH, 128>>>(P.cls, head_w, head_b, out);
}

// round 12
// speedup vs baseline: 1.0211x; 1.0211x over previous
#include <cuda_runtime.h>
#include <cuda_fp16.h>
#include <math.h>
#include <stdint.h>

#define BATCH 32
#define EMB   768
#define HEADS 12
#define HD    64
#define NLAYERS 12
#define NFIX  6
#define NADAPT 6
#define MLPD  3072
#define NCLS  100
#define NTOK  198
#define NT2   197
#define RPAD  256              // padded rows per sample in adaptive phase
#define MAXR  (BATCH*RPAD)     // 8192 rows
#define PE_NN 100
#define PE_DD 256
#define NPATCH 196

// ---------------- scratch (device globals; no allocation allowed) ------------
__device__ float g_tok [BATCH*NTOK*EMB];
__device__ __align__(16) __half g_xn  [MAXR*EMB];
__device__ __align__(16) __half g_qkv [MAXR*3*EMB];
__device__ __align__(16) __half g_attb[MAXR*EMB];
__device__ __align__(16) __half g_mlpb[MAXR*MLPD];
__device__ float g_t   [MAXR*EMB];
__device__ float g_t2  [MAXR*EMB];
__device__ __align__(16) __half g_col [BATCH*NPATCH*EMB];
__device__ float g_pat [BATCH*NPATCH*EMB];
__device__ float g_lat1[BATCH*EMB];
__device__ __align__(16) __half g_lat2[BATCH*EMB];
__device__ float g_lat3[BATCH*EMB];
__device__ __align__(16) __half g_cls [BATCH*EMB];
__device__ int   g_actv[BATCH*NADAPT];
__device__ __align__(16) __half g_wqkv [NLAYERS*3*EMB*EMB];
__device__ __align__(16) __half g_wproj[NLAYERS*EMB*EMB];
__device__ __align__(16) __half g_wfc1 [NLAYERS*MLPD*EMB];
__device__ __align__(16) __half g_wfc2 [NLAYERS*EMB*MLPD];
__device__ __align__(16) __half g_wlat2[EMB*EMB];
__device__ __align__(16) __half g_wpat [EMB*EMB];

__device__ __forceinline__ float gelu_f(float v) {
    return 0.5f * v * (1.0f + erff(v * 0.70710678118654752440f));
}
__device__ __forceinline__ uint32_t smem_u32(const void* p) {
    uint32_t a;
    asm("{ .reg .u64 t; cvta.to.shared.u64 t, %1; cvt.u32.u64 %0, t; }" : "=r"(a) : "l"(p));
    return a;
}
__device__ __forceinline__ uint32_t h2_u32(__half2 h) {
    uint32_t u;
    *(__half2*)&u = h;
    return u;
}
__device__ __forceinline__ void cp16(uint32_t dst, const void* src, bool pred) {
    int sz = pred ? 16 : 0;
    asm volatile("cp.async.cg.shared.global [%0], [%1], 16, %2;"
                 :: "r"(dst), "l"(src), "r"(sz) : "memory");
}
__device__ __forceinline__ void mma_f16(float c[4], const uint32_t a[4], const uint32_t b[2]) {
    asm volatile(
        "mma.sync.aligned.m16n8k16.row.col.f32.f16.f16.f32 "
        "{%0,%1,%2,%3}, {%4,%5,%6,%7}, {%8,%9}, {%0,%1,%2,%3};\n"
        : "+f"(c[0]), "+f"(c[1]), "+f"(c[2]), "+f"(c[3])
        : "r"(a[0]), "r"(a[1]), "r"(a[2]), "r"(a[3]), "r"(b[0]), "r"(b[1]));
}
__device__ __forceinline__ void ldsm_x4(uint32_t r[4], uint32_t addr) {
    asm volatile("ldmatrix.sync.aligned.m8n8.x4.shared.b16 {%0,%1,%2,%3}, [%4];"
                 : "=r"(r[0]), "=r"(r[1]), "=r"(r[2]), "=r"(r[3]) : "r"(addr));
}

// ---------------- fp16 tensor-core GEMM: C = A[M,K] @ Bt[N,K]^T -------------
// 128x128x64 tiles, 2-stage cp.async double buffer, ldmatrix fragment loads.
// gate: per-sample active flags; gate_rows also gates epilogue row writes.
#define HST2 72                               // halves per smem row (144 B)
#define GSTAGE (128 * HST2)                   // halves per stage per operand
#define GEMM_SMEM_BYTES (4 * GSTAGE * 2)      // 73728 (2 stages x A,B)
template<int ACT, bool RES, bool OUTH>
__global__ void __launch_bounds__(256) hgemm_k(
    const __half* __restrict__ A, const __half* __restrict__ Bt,
    const float* __restrict__ bias, const float* __restrict__ res,
    float* __restrict__ Cf, __half* __restrict__ Ch, int M, int N, int K,
    const int* __restrict__ gate, int gstride, int rps, int gate_rows)
{
    const int brow = blockIdx.y * 128;
    if (gate) {
        const int s0 = brow / rps;
        const int s1 = min(brow + 127, M - 1) / rps;
        bool any = false;
        for (int s = s0; s <= s1; s++) any |= (gate[s * gstride] != 0);
        if (!any) return;
    }

    extern __shared__ __align__(16) __half hsm[];
    const uint32_t saU[2] = { smem_u32(hsm),              smem_u32(hsm + 2 * GSTAGE) };
    const uint32_t sbU[2] = { smem_u32(hsm + GSTAGE),     smem_u32(hsm + 3 * GSTAGE) };

    const int tid  = threadIdx.x;
    const int warp = tid >> 5, lane = tid & 31;
    const int bcol = blockIdx.x * 128;
    const int warpM = (warp >> 2) * 64;
    const int warpN = (warp & 3) * 32;
    const int g4 = lane >> 2, l2 = (lane & 3) * 2;

    // per-lane ldmatrix row/col offset (halves)
    const int lmoff = ((lane & 7) + ((lane >> 3) & 1) * 8) * HST2 + (lane >> 4) * 8;

    float acc[4][4][4];
    #pragma unroll
    for (int i = 0; i < 4; i++)
        #pragma unroll
        for (int j = 0; j < 4; j++)
            #pragma unroll
            for (int r = 0; r < 4; r++) acc[i][j][r] = 0.0f;

    const int nch = K >> 6;                   // 64-K chunks

    auto LOAD = [&](int chunk, int st) {
        const int k0 = chunk << 6;
        const uint32_t da = saU[st], db = sbU[st];
        #pragma unroll
        for (int i = 0; i < 4; i++) {
            const int ch  = i * 256 + tid;    // 0..1023
            const int row = ch >> 3, col = ch & 7;
            cp16(da + row * (HST2 * 2) + col * 16,
                 A + (size_t)(brow + row) * K + k0 + col * 8, (brow + row) < M);
            cp16(db + row * (HST2 * 2) + col * 16,
                 Bt + (size_t)(bcol + row) * K + k0 + col * 8, true);
        }
        asm volatile("cp.async.commit_group;" ::: "memory");
    };

    LOAD(0, 0);

    for (int c = 0; c < nch; c++) {
        const int st = c & 1;
        if (c + 1 < nch) {
            LOAD(c + 1, st ^ 1);
            asm volatile("cp.async.wait_group 1;" ::: "memory");
        } else {
            asm volatile("cp.async.wait_group 0;" ::: "memory");
        }
        __syncthreads();

        const uint32_t aB = saU[st], bB = sbU[st];
        #pragma unroll
        for (int ks = 0; ks < 4; ks++) {
            uint32_t af[4][4], bf[4][2];
            #pragma unroll
            for (int tm = 0; tm < 4; tm++)
                ldsm_x4(af[tm], aB + 2 * ((warpM + tm * 16) * HST2 + ks * 16 + lmoff));
            #pragma unroll
            for (int tnp = 0; tnp < 2; tnp++) {
                uint32_t rb[4];
                ldsm_x4(rb, bB + 2 * ((warpN + tnp * 16) * HST2 + ks * 16 + lmoff));
                bf[2 * tnp][0]     = rb[0];
                bf[2 * tnp + 1][0] = rb[1];
                bf[2 * tnp][1]     = rb[2];
                bf[2 * tnp + 1][1] = rb[3];
            }
            #pragma unroll
            for (int tm = 0; tm < 4; tm++)
                #pragma unroll
                for (int tn = 0; tn < 4; tn++)
                    mma_f16(acc[tm][tn], af[tm], bf[tn]);
        }
        __syncthreads();
    }

    #pragma unroll
    for (int tm = 0; tm < 4; tm++) {
        const int rr = brow + warpM + tm * 16 + g4;
        #pragma unroll
        for (int half = 0; half < 2; half++) {
            const int gr = rr + half * 8;
            if (gr >= M) continue;
            if (gate_rows && gate && !gate[(gr / rps) * gstride]) continue;
            #pragma unroll
            for (int tn = 0; tn < 4; tn++) {
                const int gc = bcol + warpN + tn * 8 + l2;
                float o0 = acc[tm][tn][half * 2 + 0] + bias[gc];
                float o1 = acc[tm][tn][half * 2 + 1] + bias[gc + 1];
                if (ACT == 1) { o0 = gelu_f(o0); o1 = gelu_f(o1); }
                if (RES) {
                    o0 += res[(size_t)gr * N + gc];
                    o1 += res[(size_t)gr * N + gc + 1];
                }
                if (OUTH) {
                    *(__half2*)&Ch[(size_t)gr * N + gc] = __floats2half2_rn(o0, o1);
                } else {
                    Cf[(size_t)gr * N + gc]     = o0;
                    Cf[(size_t)gr * N + gc + 1] = o1;
                }
            }
        }
    }
}

// ---------------- weight transpose+convert ----------------------------------
__global__ void transpose_k(const float* __restrict__ in, __half* __restrict__ out,
                            int K, int N)
{
    __shared__ float t[32][33];
    const int l = blockIdx.z;
    const float* ip = in  + (size_t)l * K * N;
    __half*      op = out + (size_t)l * K * N;
    const int k0 = blockIdx.y * 32, n0 = blockIdx.x * 32;
    #pragma unroll
    for (int i = 0; i < 32; i += 8) {
        int k = k0 + threadIdx.y + i, n = n0 + threadIdx.x;
        if (k < K && n < N) t[threadIdx.y + i][threadIdx.x] = ip[(size_t)k * N + n];
    }
    __syncthreads();
    #pragma unroll
    for (int i = 0; i < 32; i += 8) {
        int n = n0 + threadIdx.y + i, k = k0 + threadIdx.x;
        if (n < N && k < K) op[(size_t)n * K + k] = __float2half_rn(t[threadIdx.x][threadIdx.y + i]);
    }
}

__global__ void cvt_k(const float* __restrict__ in, __half* __restrict__ out, long n)
{
    long i = (long)blockIdx.x * blockDim.x + threadIdx.x;
    if (i < n) out[i] = __float2half_rn(in[i]);
}

// ---------------- LayerNorm over 768 (fp32 in, half out), gated -------------
// vr: valid rows per sample (rows with row%rps >= vr are skipped).
__global__ void __launch_bounds__(192) ln_k(
    const float* __restrict__ X, long istride,
    const float* __restrict__ g, const float* __restrict__ b,
    __half* __restrict__ Y, long ostride,
    const int* __restrict__ gate, int gstride, int rps, int vr)
{
    const int row = blockIdx.x;
    const int smp = row / rps;
    if ((row - smp * rps) >= vr) return;
    if (gate && !gate[smp * gstride]) return;
    const int tid = threadIdx.x;
    const float* x = X + (size_t)row * istride;
    __half* y      = Y + (size_t)row * ostride;
    __shared__ float red[6];
    __shared__ float stat[2];

    const float4 v = *(const float4*)&x[tid * 4];
    float s = v.x + v.y + v.z + v.w;
    #pragma unroll
    for (int o = 16; o; o >>= 1) s += __shfl_xor_sync(~0u, s, o);
    if ((tid & 31) == 0) red[tid >> 5] = s;
    __syncthreads();
    if (tid == 0) {
        float t = 0.f;
        #pragma unroll
        for (int i = 0; i < 6; i++) t += red[i];
        stat[0] = t * (1.0f / 768.0f);
    }
    __syncthreads();
    const float mean = stat[0];
    const float d0 = v.x - mean, d1 = v.y - mean, d2 = v.z - mean, d3 = v.w - mean;
    s = d0 * d0 + d1 * d1 + d2 * d2 + d3 * d3;
    #pragma unroll
    for (int o = 16; o; o >>= 1) s += __shfl_xor_sync(~0u, s, o);
    __syncthreads();
    if ((tid & 31) == 0) red[tid >> 5] = s;
    __syncthreads();
    if (tid == 0) {
        float t = 0.f;
        #pragma unroll
        for (int i = 0; i < 6; i++) t += red[i];
        stat[1] = rsqrtf(t * (1.0f / 768.0f) + 1e-5f);
    }
    __syncthreads();
    const float rstd = stat[1];
    const float4 gv = *(const float4*)&g[tid * 4];
    const float4 bv = *(const float4*)&b[tid * 4];
    __half2 h01 = __floats2half2_rn(d0 * rstd * gv.x + bv.x, d1 * rstd * gv.y + bv.y);
    __half2 h23 = __floats2half2_rn(d2 * rstd * gv.z + bv.z, d3 * rstd * gv.w + bv.w);
    *(__half2*)&y[tid * 4]     = h01;
    *(__half2*)&y[tid * 4 + 2] = h23;
}

// ---------------- tensor-core attention: one CTA (128 thr) per (b,h) --------
// rowstride: rows per sample in the qkv / O buffers. N: valid tokens.
#define APAD 208
#define KST  72
#define VST  216
#define ATTN_SMEM_BYTES ((2*APAD*KST + 64*VST) * 2)

__global__ void __launch_bounds__(128) attn_k(const __half* __restrict__ qkv,
                                              __half* __restrict__ O, int N, int rowstride,
                                              const int* __restrict__ gate, int gstride)
{
    const int bh = blockIdx.x;
    const int b  = bh / HEADS, h = bh % HEADS;
    if (gate && !gate[b * gstride]) return;

    extern __shared__ __half smh[];
    __half* Qs = smh;
    __half* Ks = Qs + APAD * KST;
    __half* Vt = Ks + APAD * KST;

    const int tid = threadIdx.x;
    const int w = tid >> 5, lane = tid & 31;
    const int g4 = lane >> 2, l2 = (lane & 3) * 2;
    const __half* base = qkv + (size_t)b * rowstride * (3 * EMB) + h * 64;

    for (int n = tid; n < APAD; n += 128) {
        uint4* qd = (uint4*)&Qs[n * KST];
        uint4* kd = (uint4*)&Ks[n * KST];
        if (n < N) {
            const uint4* qs = (const uint4*)(base + (size_t)n * (3 * EMB));
            const uint4* ks = (const uint4*)(base + (size_t)n * (3 * EMB) + EMB);
            #pragma unroll
            for (int i = 0; i < 8; i++) { qd[i] = qs[i]; kd[i] = ks[i]; }
        } else {
            uint4 z = make_uint4(0, 0, 0, 0);
            #pragma unroll
            for (int i = 0; i < 8; i++) { qd[i] = z; kd[i] = z; }
        }
    }
    for (int idx = tid; idx < APAD * 64; idx += 128) {
        const int n = idx >> 6, d = idx & 63;
        __half v = (n < N) ? base[(size_t)n * (3 * EMB) + 2 * EMB + d] : __ushort_as_half(0);
        Vt[d * VST + n] = v;
    }
    __syncthreads();

    for (int qt = w; qt < 13; qt += 4) {
        const int q0 = qt * 16;
        uint32_t aq[4][4];
        #pragma unroll
        for (int ks = 0; ks < 4; ks++) {
            const int kk = ks * 16 + l2;
            aq[ks][0] = *(const uint32_t*)&Qs[(q0 + g4) * KST + kk];
            aq[ks][1] = *(const uint32_t*)&Qs[(q0 + g4 + 8) * KST + kk];
            aq[ks][2] = *(const uint32_t*)&Qs[(q0 + g4) * KST + kk + 8];
            aq[ks][3] = *(const uint32_t*)&Qs[(q0 + g4 + 8) * KST + kk + 8];
        }
        float sc[26][4];
        #pragma unroll
        for (int nt = 0; nt < 26; nt++) {
            sc[nt][0] = sc[nt][1] = sc[nt][2] = sc[nt][3] = 0.f;
            #pragma unroll
            for (int ks = 0; ks < 4; ks++) {
                const int kk = ks * 16 + l2;
                uint32_t bf[2];
                bf[0] = *(const uint32_t*)&Ks[(nt * 8 + g4) * KST + kk];
                bf[1] = *(const uint32_t*)&Ks[(nt * 8 + g4) * KST + kk + 8];
                mma_f16(sc[nt], aq[ks], bf);
            }
        }
        float m0 = -1e30f, m1 = -1e30f;
        #pragma unroll
        for (int nt = 0; nt < 26; nt++) {
            #pragma unroll
            for (int e = 0; e < 2; e++) {
                const int col = nt * 8 + l2 + e;
                const bool ok = col < N;
                float v0 = ok ? sc[nt][e]     * 0.125f : -1e30f;
                float v1 = ok ? sc[nt][2 + e] * 0.125f : -1e30f;
                sc[nt][e] = v0; sc[nt][2 + e] = v1;
                m0 = fmaxf(m0, v0); m1 = fmaxf(m1, v1);
            }
        }
        m0 = fmaxf(m0, __shfl_xor_sync(~0u, m0, 1));
        m0 = fmaxf(m0, __shfl_xor_sync(~0u, m0, 2));
        m1 = fmaxf(m1, __shfl_xor_sync(~0u, m1, 1));
        m1 = fmaxf(m1, __shfl_xor_sync(~0u, m1, 2));
        float s0 = 0.f, s1 = 0.f;
        #pragma unroll
        for (int nt = 0; nt < 26; nt++) {
            #pragma unroll
            for (int e = 0; e < 2; e++) {
                float e0 = __expf(sc[nt][e]     - m0);
                float e1 = __expf(sc[nt][2 + e] - m1);
                sc[nt][e] = e0; sc[nt][2 + e] = e1;
                s0 += e0; s1 += e1;
            }
        }
        s0 += __shfl_xor_sync(~0u, s0, 1); s0 += __shfl_xor_sync(~0u, s0, 2);
        s1 += __shfl_xor_sync(~0u, s1, 1); s1 += __shfl_xor_sync(~0u, s1, 2);
        const float i0 = 1.0f / s0, i1 = 1.0f / s1;
        float o[8][4];
        #pragma unroll
        for (int dt = 0; dt < 8; dt++) o[dt][0] = o[dt][1] = o[dt][2] = o[dt][3] = 0.f;
        #pragma unroll
        for (int kt = 0; kt < 13; kt++) {
            uint32_t ap[4];
            ap[0] = h2_u32(__floats2half2_rn(sc[2*kt][0]   * i0, sc[2*kt][1]   * i0));
            ap[1] = h2_u32(__floats2half2_rn(sc[2*kt][2]   * i1, sc[2*kt][3]   * i1));
            ap[2] = h2_u32(__floats2half2_rn(sc[2*kt+1][0] * i0, sc[2*kt+1][1] * i0));
            ap[3] = h2_u32(__floats2half2_rn(sc[2*kt+1][2] * i1, sc[2*kt+1][3] * i1));
            #pragma unroll
            for (int dt = 0; dt < 8; dt++) {
                uint32_t bv[2];
                bv[0] = *(const uint32_t*)&Vt[(dt * 8 + g4) * VST + kt * 16 + l2];
                bv[1] = *(const uint32_t*)&Vt[(dt * 8 + g4) * VST + kt * 16 + l2 + 8];
                mma_f16(o[dt], ap, bv);
            }
        }
        const int r0 = q0 + g4, r1 = q0 + g4 + 8;
        __half* ob = O + (size_t)b * rowstride * EMB + h * 64;
        #pragma unroll
        for (int dt = 0; dt < 8; dt++) {
            const int c = dt * 8 + l2;
            if (r0 < N)
                *(__half2*)&ob[(size_t)r0 * EMB + c] = __floats2half2_rn(o[dt][0], o[dt][1]);
            if (r1 < N)
                *(__half2*)&ob[(size_t)r1 * EMB + c] = __floats2half2_rn(o[dt][2], o[dt][3]);
        }
    }
}

// ---------------- small / elementwise kernels -------------------------------
__global__ void im2col_k(const float* __restrict__ x, __half* __restrict__ col, long total)
{
    long i = (long)blockIdx.x * blockDim.x + threadIdx.x;
    if (i >= total) return;
    int k = (int)(i % EMB);
    long m = i / EMB;
    int b = (int)(m / NPATCH), p = (int)(m % NPATCH);
    int c = k >> 8, r = k & 255, ii = r >> 4, jj = r & 15;
    int py = p / 14, px = p % 14;
    col[i] = __float2half_rn(x[(((size_t)b * 3 + c) * 224 + py * 16 + ii) * 224 + px * 16 + jj]);
}

__global__ void lat1_k(const float* __restrict__ pe, const float* __restrict__ w1,
                       const float* __restrict__ b1, const float* __restrict__ budget,
                       float* __restrict__ out)
{
    int b = blockIdx.x;
    int idx = (int)rintf(budget[b] * (float)(PE_NN - 1));
    const float* row = pe + (size_t)idx * PE_DD;
    for (int e = threadIdx.x; e < EMB; e += 256) {
        float s = b1[e];
        for (int k = 0; k < PE_DD; k++) s += row[k] * w1[(size_t)k * EMB + e];
        out[(size_t)b * EMB + e] = gelu_f(s);
    }
}

__global__ void assemble_k(const float* __restrict__ lat, const float* __restrict__ cls,
                           const float* __restrict__ pat, const float* __restrict__ pos,
                           float* __restrict__ tok, long total)
{
    long i = (long)blockIdx.x * blockDim.x + threadIdx.x;
    if (i >= total) return;
    int e = (int)(i % EMB);
    long bn = i / EMB;
    int n = (int)(bn % NTOK), b = (int)(bn / NTOK);
    float v;
    if (n == 0)      v = lat[(size_t)b * EMB + e];
    else if (n == 1) v = cls[e];
    else             v = pat[((size_t)b * NPATCH + (n - 2)) * EMB + e];
    tok[i] = v + pos[(size_t)n * EMB + e];
}

__global__ void sched_k(const float* __restrict__ tok, const float* __restrict__ sw,
                        const float* __restrict__ sb, const float* __restrict__ budget,
                        int* __restrict__ active)
{
    int b = blockIdx.x, lane = threadIdx.x;
    __shared__ float lg[NADAPT];
    if (lane < NADAPT) {
        const float* x = tok + (size_t)b * NTOK * EMB;
        float s = sb[lane];
        for (int k = 0; k < EMB; k++) s += x[k] * sw[(size_t)k * NADAPT + lane];
        lg[lane] = s;
    }
    __syncwarp();
    if (lane < NADAPT) {
        int kk = (int)ceilf(budget[b] * (float)NADAPT);
        if (kk < 1) kk = 1;
        int rank = 0;
        for (int j = 0; j < NADAPT; j++)
            if (lg[j] > lg[lane] || (lg[j] == lg[lane] && j < lane)) rank++;
        active[b * NADAPT + lane] = (rank < kk) ? 1 : 0;
    }
}

// extract tokens 1..197 of each sample into padded layout (RPAD rows/sample)
__global__ void extract_k(const float* __restrict__ tok, float* __restrict__ t, long total)
{
    long i = (long)blockIdx.x * blockDim.x + threadIdx.x;
    if (i >= total) return;
    int e = (int)(i % EMB);
    long bn = i / EMB;
    int n = (int)(bn % NT2), b = (int)(bn / NT2);
    t[((size_t)b * RPAD + n) * EMB + e] = tok[((size_t)b * NTOK + n + 1) * EMB + e];
}

__global__ void head_k(const __half* __restrict__ cls, const float* __restrict__ w,
                       const float* __restrict__ bias, float* __restrict__ out)
{
    int b = blockIdx.x, c = threadIdx.x;
    if (c >= NCLS) return;
    const __half* x = cls + (size_t)b * EMB;
    float s = bias[c];
    for (int k = 0; k < EMB; k++) s += __half2float(x[k]) * w[(size_t)k * NCLS + c];
    out[(size_t)b * NCLS + c] = s;
}

// ---------------- host orchestration ----------------------------------------
static inline void launch_gemm(int act, bool res, bool outh,
                               const __half* A, const __half* Bt, const float* bias,
                               const float* r, float* Cf, __half* Ch, int M, int N, int K,
                               const int* gate, int gstride, int rps, int gate_rows)
{
    dim3 g(N / 128, (M + 127) / 128), blk(256);
    if (outh) {
        if (act == 1)      hgemm_k<1, false, true><<<g, blk, GEMM_SMEM_BYTES>>>(A, Bt, bias, r, Cf, Ch, M, N, K, gate, gstride, rps, gate_rows);
        else               hgemm_k<0, false, true><<<g, blk, GEMM_SMEM_BYTES>>>(A, Bt, bias, r, Cf, Ch, M, N, K, gate, gstride, rps, gate_rows);
    } else {
        if (res)           hgemm_k<0, true,  false><<<g, blk, GEMM_SMEM_BYTES>>>(A, Bt, bias, r, Cf, Ch, M, N, K, gate, gstride, rps, gate_rows);
        else               hgemm_k<0, false, false><<<g, blk, GEMM_SMEM_BYTES>>>(A, Bt, bias, r, Cf, Ch, M, N, K, gate, gstride, rps, gate_rows);
    }
}

struct Ptrs {
    float *tok, *t, *t2, *pat, *lat1, *lat3;
    __half *xn, *qkv, *att, *mlp, *col, *lat2, *cls;
    __half *wqkv, *wproj, *wfc1, *wfc2, *wlat2, *wpat;
    int   *actv;
};

// rps: rows per sample (incl. padding), vr: valid rows per sample.
static void run_block(const Ptrs& P, float* Xin, float* Xmid, float* Xout,
                      int rps, int vr, int l,
                      const float* ln1g, const float* ln1b, const float* qkvb,
                      const float* projb, const float* ln2g, const float* ln2b,
                      const float* fc1b, const float* fc2b,
                      const int* gate, int gstride, int gate_rows)
{
    const int M = BATCH * rps;
    ln_k<<<M, 192>>>(Xin, EMB, ln1g + (size_t)l * EMB, ln1b + (size_t)l * EMB,
                     P.xn, EMB, gate, gstride, rps, vr);
    launch_gemm(0, false, true, P.xn, P.wqkv + (size_t)l * EMB * 3 * EMB,
                qkvb + (size_t)l * 3 * EMB, nullptr, nullptr, P.qkv, M, 3 * EMB, EMB,
                gate, gstride, rps, 0);
    attn_k<<<BATCH * HEADS, 128, ATTN_SMEM_BYTES>>>(P.qkv, P.att, vr, rps, gate, gstride);
    launch_gemm(0, true, false, P.att, P.wproj + (size_t)l * EMB * EMB,
                projb + (size_t)l * EMB, Xin, Xmid, nullptr, M, EMB, EMB,
                gate, gstride, rps, 0);
    ln_k<<<M, 192>>>(Xmid, EMB, ln2g + (size_t)l * EMB, ln2b + (size_t)l * EMB,
                     P.xn, EMB, gate, gstride, rps, vr);
    launch_gemm(1, false, true, P.xn, P.wfc1 + (size_t)l * EMB * MLPD,
                fc1b + (size_t)l * MLPD, nullptr, nullptr, P.mlp, M, MLPD, EMB,
                gate, gstride, rps, 0);
    launch_gemm(0, true, false, P.mlp, P.wfc2 + (size_t)l * MLPD * EMB,
                fc2b + (size_t)l * EMB, Xmid, Xout, nullptr, M, EMB, MLPD,
                gate, gstride, rps, gate_rows);
}

extern "C" void kernel_launch(void* const* d_in, const int* in_sizes, int n_in,
                              void* d_out, int out_size)
{
    const float* x        = (const float*)d_in[0];
    const float* budget   = (const float*)d_in[1];
    const float* pe_table = (const float*)d_in[2];
    const float* lat_w1   = (const float*)d_in[3];
    const float* lat_b1   = (const float*)d_in[4];
    const float* lat_ln_g = (const float*)d_in[5];
    const float* lat_ln_b = (const float*)d_in[6];
    const float* lat_w2   = (const float*)d_in[7];
    const float* lat_b2   = (const float*)d_in[8];
    const float* patch_w  = (const float*)d_in[9];
    const float* patch_b  = (const float*)d_in[10];
    const float* cls_tok  = (const float*)d_in[11];
    const float* pos_emb  = (const float*)d_in[12];
    const float* sched_w  = (const float*)d_in[13];
    const float* sched_b  = (const float*)d_in[14];
    const float* ln1_g    = (const float*)d_in[15];
    const float* ln1_b    = (const float*)d_in[16];
    const float* qkv_w    = (const float*)d_in[17];
    const float* qkv_b    = (const float*)d_in[18];
    const float* proj_w   = (const float*)d_in[19];
    const float* proj_b   = (const float*)d_in[20];
    const float* ln2_g    = (const float*)d_in[21];
    const float* ln2_b    = (const float*)d_in[22];
    const float* fc1_w    = (const float*)d_in[23];
    const float* fc1_b    = (const float*)d_in[24];
    const float* fc2_w    = (const float*)d_in[25];
    const float* fc2_b    = (const float*)d_in[26];
    const float* norm_g   = (const float*)d_in[27];
    const float* norm_b   = (const float*)d_in[28];
    const float* head_w   = (const float*)d_in[29];
    const float* head_b   = (const float*)d_in[30];
    float* out = (float*)d_out;

    Ptrs P;
    cudaGetSymbolAddress((void**)&P.tok,  g_tok);
    cudaGetSymbolAddress((void**)&P.xn,   g_xn);
    cudaGetSymbolAddress((void**)&P.qkv,  g_qkv);
    cudaGetSymbolAddress((void**)&P.att,  g_attb);
    cudaGetSymbolAddress((void**)&P.mlp,  g_mlpb);
    cudaGetSymbolAddress((void**)&P.t,    g_t);
    cudaGetSymbolAddress((void**)&P.t2,   g_t2);
    cudaGetSymbolAddress((void**)&P.col,  g_col);
    cudaGetSymbolAddress((void**)&P.pat,  g_pat);
    cudaGetSymbolAddress((void**)&P.lat1, g_lat1);
    cudaGetSymbolAddress((void**)&P.lat2, g_lat2);
    cudaGetSymbolAddress((void**)&P.lat3, g_lat3);
    cudaGetSymbolAddress((void**)&P.cls,  g_cls);
    cudaGetSymbolAddress((void**)&P.actv, g_actv);
    cudaGetSymbolAddress((void**)&P.wqkv, g_wqkv);
    cudaGetSymbolAddress((void**)&P.wproj,g_wproj);
    cudaGetSymbolAddress((void**)&P.wfc1, g_wfc1);
    cudaGetSymbolAddress((void**)&P.wfc2, g_wfc2);
    cudaGetSymbolAddress((void**)&P.wlat2,g_wlat2);
    cudaGetSymbolAddress((void**)&P.wpat, g_wpat);

    cudaFuncSetAttribute(attn_k, cudaFuncAttributeMaxDynamicSharedMemorySize, ATTN_SMEM_BYTES);
    cudaFuncSetAttribute(hgemm_k<0,false,true >, cudaFuncAttributeMaxDynamicSharedMemorySize, GEMM_SMEM_BYTES);
    cudaFuncSetAttribute(hgemm_k<1,false,true >, cudaFuncAttributeMaxDynamicSharedMemorySize, GEMM_SMEM_BYTES);
    cudaFuncSetAttribute(hgemm_k<0,true, false>, cudaFuncAttributeMaxDynamicSharedMemorySize, GEMM_SMEM_BYTES);
    cudaFuncSetAttribute(hgemm_k<0,false,false>, cudaFuncAttributeMaxDynamicSharedMemorySize, GEMM_SMEM_BYTES);

    // --- weight transposes+convert ([K,N] fp32 -> [N,K] half) ---
    {
        dim3 b32(32, 8);
        transpose_k<<<dim3(3*EMB/32, EMB/32, NLAYERS), b32>>>(qkv_w,  P.wqkv,  EMB, 3*EMB);
        transpose_k<<<dim3(EMB/32,   EMB/32, NLAYERS), b32>>>(proj_w, P.wproj, EMB, EMB);
        transpose_k<<<dim3(MLPD/32,  EMB/32, NLAYERS), b32>>>(fc1_w,  P.wfc1,  EMB, MLPD);
        transpose_k<<<dim3(EMB/32,  MLPD/32, NLAYERS), b32>>>(fc2_w,  P.wfc2,  MLPD, EMB);
        transpose_k<<<dim3(EMB/32,   EMB/32, 1),       b32>>>(lat_w2, P.wlat2, EMB, EMB);
        long pw = (long)EMB * EMB;
        cvt_k<<<(unsigned)((pw + 255) / 256), 256>>>(patch_w, P.wpat, pw);
    }

    // --- latent token ---
    lat1_k<<<BATCH, 256>>>(pe_table, lat_w1, lat_b1, budget, P.lat1);
    ln_k<<<BATCH, 192>>>(P.lat1, EMB, lat_ln_g, lat_ln_b, P.lat2, EMB, nullptr, 0, 1, 1);
    launch_gemm(0, false, false, P.lat2, P.wlat2, lat_b2, nullptr, P.lat3, nullptr,
                BATCH, EMB, EMB, nullptr, 0, 1, 0);

    // --- patch embedding ---
    {
        long tot = (long)BATCH * NPATCH * EMB;
        im2col_k<<<(unsigned)((tot + 255) / 256), 256>>>(x, P.col, tot);
        launch_gemm(0, false, false, P.col, P.wpat, patch_b, nullptr, P.pat, nullptr,
                    BATCH * NPATCH, EMB, EMB, nullptr, 0, 1, 0);
        long ta = (long)BATCH * NTOK * EMB;
        assemble_k<<<(unsigned)((ta + 255) / 256), 256>>>(P.lat3, cls_tok, P.pat,
                                                          pos_emb, P.tok, ta);
    }

    // --- 6 fixed blocks on 198 tokens (contiguous layout, in-place on tok) ---
    for (int l = 0; l < NFIX; l++)
        run_block(P, P.tok, P.tok, P.tok, NTOK, NTOK, l, ln1_g, ln1_b, qkv_b, proj_b,
                  ln2_g, ln2_b, fc1_b, fc2_b, nullptr, 0, 0);

    // --- scheduler gating ---
    sched_k<<<BATCH, 32>>>(P.tok, sched_w, sched_b, budget, P.actv);

    // --- adaptive blocks on 197 tokens, RPAD-padded layout for exact tile gating
    const long tlen = (long)BATCH * NT2 * EMB;
    extract_k<<<(unsigned)((tlen + 255) / 256), 256>>>(P.tok, P.t, tlen);
    for (int i = 0; i < NADAPT; i++) {
        const int* gate = P.actv + i;    // gate[s * NADAPT] = active[s][i]
        run_block(P, P.t, P.t2, P.t, RPAD, NT2, NFIX + i, ln1_g, ln1_b, qkv_b, proj_b,
                  ln2_g, ln2_b, fc1_b, fc2_b, gate, NADAPT, 1);
    }

    // --- final LN on token 0 of each sample (padded stride) + head ---
    ln_k<<<BATCH, 192>>>(P.t, (long)RPAD * EMB, norm_g, norm_b, P.cls, EMB,
                         nullptr, 0, 1, 1);
    head_k<<<BATCH, 128>>>(P.cls, head_w, head_b, out);
}

// round 13
// speedup vs baseline: 1.0595x; 1.0376x over previous
#include <cuda_runtime.h>
#include <cuda_fp16.h>
#include <math.h>
#include <stdint.h>

#define BATCH 32
#define EMB   768
#define HEADS 12
#define HD    64
#define NLAYERS 12
#define NFIX  6
#define NADAPT 6
#define MLPD  3072
#define NCLS  100
#define NTOK  198
#define NT2   197
#define PE_NN 100
#define PE_DD 256
#define NPATCH 196

// ---------------- scratch (device globals; no allocation allowed) ------------
__device__ float g_tok [BATCH*NTOK*EMB];
__device__ __align__(16) __half g_xn  [BATCH*NTOK*EMB];
__device__ __align__(16) __half g_qkv [BATCH*NTOK*3*EMB];
__device__ __align__(16) __half g_attb[BATCH*NTOK*EMB];
__device__ __align__(16) __half g_mlpb[BATCH*NTOK*MLPD];
__device__ float g_t   [BATCH*NT2*EMB];
__device__ float g_t2  [BATCH*NT2*EMB];
__device__ __align__(16) __half g_col [BATCH*NPATCH*EMB];
__device__ float g_pat [BATCH*NPATCH*EMB];
__device__ float g_lat1[BATCH*EMB];
__device__ __align__(16) __half g_lat2[BATCH*EMB];
__device__ float g_lat3[BATCH*EMB];
__device__ __align__(16) __half g_cls [BATCH*EMB];
__device__ int   g_actv[BATCH*NADAPT];
__device__ __align__(16) __half g_wqkv [NLAYERS*3*EMB*EMB];
__device__ __align__(16) __half g_wproj[NLAYERS*EMB*EMB];
__device__ __align__(16) __half g_wfc1 [NLAYERS*MLPD*EMB];
__device__ __align__(16) __half g_wfc2 [NLAYERS*EMB*MLPD];
__device__ __align__(16) __half g_wlat2[EMB*EMB];
__device__ __align__(16) __half g_wpat [EMB*EMB];

__device__ __forceinline__ float gelu_f(float v) {
    return 0.5f * v * (1.0f + erff(v * 0.70710678118654752440f));
}
__device__ __forceinline__ uint32_t smem_u32(const void* p) {
    uint32_t a;
    asm("{ .reg .u64 t; cvta.to.shared.u64 t, %1; cvt.u32.u64 %0, t; }" : "=r"(a) : "l"(p));
    return a;
}
__device__ __forceinline__ uint32_t h2_u32(__half2 h) {
    uint32_t u;
    *(__half2*)&u = h;
    return u;
}
__device__ __forceinline__ void cp16(uint32_t dst, const void* src, bool pred) {
    int sz = pred ? 16 : 0;
    asm volatile("cp.async.cg.shared.global [%0], [%1], 16, %2;"
                 :: "r"(dst), "l"(src), "r"(sz) : "memory");
}
__device__ __forceinline__ void mma_f16(float c[4], const uint32_t a[4], const uint32_t b[2]) {
    asm volatile(
        "mma.sync.aligned.m16n8k16.row.col.f32.f16.f16.f32 "
        "{%0,%1,%2,%3}, {%4,%5,%6,%7}, {%8,%9}, {%0,%1,%2,%3};\n"
        : "+f"(c[0]), "+f"(c[1]), "+f"(c[2]), "+f"(c[3])
        : "r"(a[0]), "r"(a[1]), "r"(a[2]), "r"(a[3]), "r"(b[0]), "r"(b[1]));
}
__device__ __forceinline__ void ldsm_x4(uint32_t r[4], uint32_t addr) {
    asm volatile("ldmatrix.sync.aligned.m8n8.x4.shared.b16 {%0,%1,%2,%3}, [%4];"
                 : "=r"(r[0]), "=r"(r[1]), "=r"(r[2]), "=r"(r[3]) : "r"(addr));
}

// ---------------- fp16 tensor-core GEMM: C = A[M,K] @ Bt[N,K]^T -------------
// 128x128x64 tiles, 2-stage cp.async double buffer, ldmatrix fragment loads.
// gate: per-sample active flags; gate_rows also gates epilogue row writes.
#define HST2 72                               // halves per smem row (144 B)
#define GSTAGE (128 * HST2)                   // halves per stage per operand
#define GEMM_SMEM_BYTES (4 * GSTAGE * 2)      // 73728
template<int ACT, bool RES, bool OUTH>
__global__ void __launch_bounds__(256) hgemm_k(
    const __half* __restrict__ A, const __half* __restrict__ Bt,
    const float* __restrict__ bias, const float* __restrict__ res,
    float* __restrict__ Cf, __half* __restrict__ Ch, int M, int N, int K,
    const int* __restrict__ gate, int gstride, int rps, int gate_rows)
{
    const int brow = blockIdx.y * 128;
    if (gate) {
        const int s0 = brow / rps;
        const int s1 = min(brow + 127, M - 1) / rps;
        bool any = false;
        for (int s = s0; s <= s1; s++) any |= (gate[s * gstride] != 0);
        if (!any) return;
    }

    extern __shared__ __align__(16) __half hsm[];
    const uint32_t saU[2] = { smem_u32(hsm),          smem_u32(hsm + 2 * GSTAGE) };
    const uint32_t sbU[2] = { smem_u32(hsm + GSTAGE), smem_u32(hsm + 3 * GSTAGE) };

    const int tid  = threadIdx.x;
    const int warp = tid >> 5, lane = tid & 31;
    const int bcol = blockIdx.x * 128;
    const int warpM = (warp >> 2) * 64;
    const int warpN = (warp & 3) * 32;
    const int g4 = lane >> 2, l2 = (lane & 3) * 2;

    // per-lane ldmatrix row/col offset (halves)
    const int lmoff = ((lane & 7) + ((lane >> 3) & 1) * 8) * HST2 + (lane >> 4) * 8;

    float acc[4][4][4];
    #pragma unroll
    for (int i = 0; i < 4; i++)
        #pragma unroll
        for (int j = 0; j < 4; j++)
            #pragma unroll
            for (int r = 0; r < 4; r++) acc[i][j][r] = 0.0f;

    const int nch = K >> 6;                   // 64-K chunks

    auto LOAD = [&](int chunk, int st) {
        const int k0 = chunk << 6;
        const uint32_t da = saU[st], db = sbU[st];
        #pragma unroll
        for (int i = 0; i < 4; i++) {
            const int ch  = i * 256 + tid;    // 0..1023
            const int row = ch >> 3, col = ch & 7;
            cp16(da + row * (HST2 * 2) + col * 16,
                 A + (size_t)(brow + row) * K + k0 + col * 8, (brow + row) < M);
            cp16(db + row * (HST2 * 2) + col * 16,
                 Bt + (size_t)(bcol + row) * K + k0 + col * 8, true);
        }
        asm volatile("cp.async.commit_group;" ::: "memory");
    };

    LOAD(0, 0);

    for (int c = 0; c < nch; c++) {
        const int st = c & 1;
        if (c + 1 < nch) {
            LOAD(c + 1, st ^ 1);
            asm volatile("cp.async.wait_group 1;" ::: "memory");
        } else {
            asm volatile("cp.async.wait_group 0;" ::: "memory");
        }
        __syncthreads();

        const uint32_t aB = saU[st], bB = sbU[st];
        #pragma unroll
        for (int ks = 0; ks < 4; ks++) {
            uint32_t af[4][4], bf[4][2];
            #pragma unroll
            for (int tm = 0; tm < 4; tm++)
                ldsm_x4(af[tm], aB + 2 * ((warpM + tm * 16) * HST2 + ks * 16 + lmoff));
            #pragma unroll
            for (int tnp = 0; tnp < 2; tnp++) {
                uint32_t rb[4];
                ldsm_x4(rb, bB + 2 * ((warpN + tnp * 16) * HST2 + ks * 16 + lmoff));
                bf[2 * tnp][0]     = rb[0];
                bf[2 * tnp + 1][0] = rb[1];
                bf[2 * tnp][1]     = rb[2];
                bf[2 * tnp + 1][1] = rb[3];
            }
            #pragma unroll
            for (int tm = 0; tm < 4; tm++)
                #pragma unroll
                for (int tn = 0; tn < 4; tn++)
                    mma_f16(acc[tm][tn], af[tm], bf[tn]);
        }
        __syncthreads();
    }

    #pragma unroll
    for (int tm = 0; tm < 4; tm++) {
        const int rr = brow + warpM + tm * 16 + g4;
        #pragma unroll
        for (int half = 0; half < 2; half++) {
            const int gr = rr + half * 8;
            if (gr >= M) continue;
            if (gate_rows && gate && !gate[(gr / rps) * gstride]) continue;
            #pragma unroll
            for (int tn = 0; tn < 4; tn++) {
                const int gc = bcol + warpN + tn * 8 + l2;
                float o0 = acc[tm][tn][half * 2 + 0] + bias[gc];
                float o1 = acc[tm][tn][half * 2 + 1] + bias[gc + 1];
                if (ACT == 1) { o0 = gelu_f(o0); o1 = gelu_f(o1); }
                if (RES) {
                    o0 += res[(size_t)gr * N + gc];
                    o1 += res[(size_t)gr * N + gc + 1];
                }
                if (OUTH) {
                    *(__half2*)&Ch[(size_t)gr * N + gc] = __floats2half2_rn(o0, o1);
                } else {
                    Cf[(size_t)gr * N + gc]     = o0;
                    Cf[(size_t)gr * N + gc + 1] = o1;
                }
            }
        }
    }
}

// ---------------- weight transpose+convert, half2 stores --------------------
// out[l][n][k] = in[l][k][n]; K,N multiples of 32.
__global__ void transpose_k(const float* __restrict__ in, __half* __restrict__ out,
                            int K, int N)
{
    __shared__ float t[32][33];
    const int l = blockIdx.z;
    const float* ip = in  + (size_t)l * K * N;
    __half*      op = out + (size_t)l * K * N;
    const int k0 = blockIdx.y * 32, n0 = blockIdx.x * 32;
    const int tx = threadIdx.x, ty = threadIdx.y;    // (32, 8)
    #pragma unroll
    for (int i = 0; i < 32; i += 8) {
        int k = k0 + ty + i, n = n0 + tx;
        if (k < K && n < N) t[ty + i][tx] = ip[(size_t)k * N + n];
    }
    __syncthreads();
    const int idx = ty * 32 + tx;                    // 0..255
    #pragma unroll
    for (int rep = 0; rep < 2; rep++) {
        const int e  = rep * 256 + idx;              // 0..511
        const int nl = e >> 4;                       // 0..31
        const int k2 = e & 15;                       // 0..15
        const int n = n0 + nl, k = k0 + k2 * 2;
        if (n < N && k < K) {
            __half2 v = __floats2half2_rn(t[k2 * 2][nl], t[k2 * 2 + 1][nl]);
            *(__half2*)&op[(size_t)n * K + k] = v;
        }
    }
}

__global__ void cvt_k(const float* __restrict__ in, __half* __restrict__ out, long n)
{
    long i = (long)blockIdx.x * blockDim.x + threadIdx.x;
    if (i < n) out[i] = __float2half_rn(in[i]);
}

// ---------------- LayerNorm over 768 (fp32 in, half out), gated -------------
__global__ void __launch_bounds__(192) ln_k(
    const float* __restrict__ X, long istride,
    const float* __restrict__ g, const float* __restrict__ b,
    __half* __restrict__ Y, long ostride,
    const int* __restrict__ gate, int gstride, int rps)
{
    const int row = blockIdx.x;
    if (gate && !gate[(row / rps) * gstride]) return;
    const int tid = threadIdx.x;
    const float* x = X + (size_t)row * istride;
    __half* y      = Y + (size_t)row * ostride;
    __shared__ float red[6];
    __shared__ float stat[2];

    const float4 v = *(const float4*)&x[tid * 4];
    float s = v.x + v.y + v.z + v.w;
    #pragma unroll
    for (int o = 16; o; o >>= 1) s += __shfl_xor_sync(~0u, s, o);
    if ((tid & 31) == 0) red[tid >> 5] = s;
    __syncthreads();
    if (tid == 0) {
        float t = 0.f;
        #pragma unroll
        for (int i = 0; i < 6; i++) t += red[i];
        stat[0] = t * (1.0f / 768.0f);
    }
    __syncthreads();
    const float mean = stat[0];
    const float d0 = v.x - mean, d1 = v.y - mean, d2 = v.z - mean, d3 = v.w - mean;
    s = d0 * d0 + d1 * d1 + d2 * d2 + d3 * d3;
    #pragma unroll
    for (int o = 16; o; o >>= 1) s += __shfl_xor_sync(~0u, s, o);
    __syncthreads();
    if ((tid & 31) == 0) red[tid >> 5] = s;
    __syncthreads();
    if (tid == 0) {
        float t = 0.f;
        #pragma unroll
        for (int i = 0; i < 6; i++) t += red[i];
        stat[1] = rsqrtf(t * (1.0f / 768.0f) + 1e-5f);
    }
    __syncthreads();
    const float rstd = stat[1];
    const float4 gv = *(const float4*)&g[tid * 4];
    const float4 bv = *(const float4*)&b[tid * 4];
    __half2 h01 = __floats2half2_rn(d0 * rstd * gv.x + bv.x, d1 * rstd * gv.y + bv.y);
    __half2 h23 = __floats2half2_rn(d2 * rstd * gv.z + bv.z, d3 * rstd * gv.w + bv.w);
    *(__half2*)&y[tid * 4]     = h01;
    *(__half2*)&y[tid * 4 + 2] = h23;
}

// ---------------- tensor-core attention: one CTA (128 thr) per (b,h) --------
#define APAD 208
#define KST  72
#define VST  216
#define ATTN_SMEM_BYTES ((2*APAD*KST + 64*VST) * 2)

__global__ void __launch_bounds__(128) attn_k(const __half* __restrict__ qkv,
                                              __half* __restrict__ O, int N,
                                              const int* __restrict__ gate, int gstride)
{
    const int bh = blockIdx.x;
    const int b  = bh / HEADS, h = bh % HEADS;
    if (gate && !gate[b * gstride]) return;

    extern __shared__ __half smh[];
    __half* Qs = smh;
    __half* Ks = Qs + APAD * KST;
    __half* Vt = Ks + APAD * KST;

    const int tid = threadIdx.x;
    const int w = tid >> 5, lane = tid & 31;
    const int g4 = lane >> 2, l2 = (lane & 3) * 2;
    const __half* base = qkv + (size_t)b * N * (3 * EMB) + h * 64;

    for (int n = tid; n < APAD; n += 128) {
        uint4* qd = (uint4*)&Qs[n * KST];
        uint4* kd = (uint4*)&Ks[n * KST];
        if (n < N) {
            const uint4* qs = (const uint4*)(base + (size_t)n * (3 * EMB));
            const uint4* ks = (const uint4*)(base + (size_t)n * (3 * EMB) + EMB);
            #pragma unroll
            for (int i = 0; i < 8; i++) { qd[i] = qs[i]; kd[i] = ks[i]; }
        } else {
            uint4 z = make_uint4(0, 0, 0, 0);
            #pragma unroll
            for (int i = 0; i < 8; i++) { qd[i] = z; kd[i] = z; }
        }
    }
    for (int idx = tid; idx < APAD * 64; idx += 128) {
        const int n = idx >> 6, d = idx & 63;
        __half v = (n < N) ? base[(size_t)n * (3 * EMB) + 2 * EMB + d] : __ushort_as_half(0);
        Vt[d * VST + n] = v;
    }
    __syncthreads();

    for (int qt = w; qt < 13; qt += 4) {
        const int q0 = qt * 16;
        uint32_t aq[4][4];
        #pragma unroll
        for (int ks = 0; ks < 4; ks++) {
            const int kk = ks * 16 + l2;
            aq[ks][0] = *(const uint32_t*)&Qs[(q0 + g4) * KST + kk];
            aq[ks][1] = *(const uint32_t*)&Qs[(q0 + g4 + 8) * KST + kk];
            aq[ks][2] = *(const uint32_t*)&Qs[(q0 + g4) * KST + kk + 8];
            aq[ks][3] = *(const uint32_t*)&Qs[(q0 + g4 + 8) * KST + kk + 8];
        }
        float sc[26][4];
        #pragma unroll
        for (int nt = 0; nt < 26; nt++) {
            sc[nt][0] = sc[nt][1] = sc[nt][2] = sc[nt][3] = 0.f;
            #pragma unroll
            for (int ks = 0; ks < 4; ks++) {
                const int kk = ks * 16 + l2;
                uint32_t bf[2];
                bf[0] = *(const uint32_t*)&Ks[(nt * 8 + g4) * KST + kk];
                bf[1] = *(const uint32_t*)&Ks[(nt * 8 + g4) * KST + kk + 8];
                mma_f16(sc[nt], aq[ks], bf);
            }
        }
        float m0 = -1e30f, m1 = -1e30f;
        #pragma unroll
        for (int nt = 0; nt < 26; nt++) {
            #pragma unroll
            for (int e = 0; e < 2; e++) {
                const int col = nt * 8 + l2 + e;
                const bool ok = col < N;
                float v0 = ok ? sc[nt][e]     * 0.125f : -1e30f;
                float v1 = ok ? sc[nt][2 + e] * 0.125f : -1e30f;
                sc[nt][e] = v0; sc[nt][2 + e] = v1;
                m0 = fmaxf(m0, v0); m1 = fmaxf(m1, v1);
            }
        }
        m0 = fmaxf(m0, __shfl_xor_sync(~0u, m0, 1));
        m0 = fmaxf(m0, __shfl_xor_sync(~0u, m0, 2));
        m1 = fmaxf(m1, __shfl_xor_sync(~0u, m1, 1));
        m1 = fmaxf(m1, __shfl_xor_sync(~0u, m1, 2));
        float s0 = 0.f, s1 = 0.f;
        #pragma unroll
        for (int nt = 0; nt < 26; nt++) {
            #pragma unroll
            for (int e = 0; e < 2; e++) {
                float e0 = __expf(sc[nt][e]     - m0);
                float e1 = __expf(sc[nt][2 + e] - m1);
                sc[nt][e] = e0; sc[nt][2 + e] = e1;
                s0 += e0; s1 += e1;
            }
        }
        s0 += __shfl_xor_sync(~0u, s0, 1); s0 += __shfl_xor_sync(~0u, s0, 2);
        s1 += __shfl_xor_sync(~0u, s1, 1); s1 += __shfl_xor_sync(~0u, s1, 2);
        const float i0 = 1.0f / s0, i1 = 1.0f / s1;
        float o[8][4];
        #pragma unroll
        for (int dt = 0; dt < 8; dt++) o[dt][0] = o[dt][1] = o[dt][2] = o[dt][3] = 0.f;
        #pragma unroll
        for (int kt = 0; kt < 13; kt++) {
            uint32_t ap[4];
            ap[0] = h2_u32(__floats2half2_rn(sc[2*kt][0]   * i0, sc[2*kt][1]   * i0));
            ap[1] = h2_u32(__floats2half2_rn(sc[2*kt][2]   * i1, sc[2*kt][3]   * i1));
            ap[2] = h2_u32(__floats2half2_rn(sc[2*kt+1][0] * i0, sc[2*kt+1][1] * i0));
            ap[3] = h2_u32(__floats2half2_rn(sc[2*kt+1][2] * i1, sc[2*kt+1][3] * i1));
            #pragma unroll
            for (int dt = 0; dt < 8; dt++) {
                uint32_t bv[2];
                bv[0] = *(const uint32_t*)&Vt[(dt * 8 + g4) * VST + kt * 16 + l2];
                bv[1] = *(const uint32_t*)&Vt[(dt * 8 + g4) * VST + kt * 16 + l2 + 8];
                mma_f16(o[dt], ap, bv);
            }
        }
        const int r0 = q0 + g4, r1 = q0 + g4 + 8;
        __half* ob = O + h * 64;
        #pragma unroll
        for (int dt = 0; dt < 8; dt++) {
            const int c = dt * 8 + l2;
            if (r0 < N)
                *(__half2*)&ob[((size_t)b * N + r0) * EMB + c] = __floats2half2_rn(o[dt][0], o[dt][1]);
            if (r1 < N)
                *(__half2*)&ob[((size_t)b * N + r1) * EMB + c] = __floats2half2_rn(o[dt][2], o[dt][3]);
        }
    }
}

// ---------------- small / elementwise kernels -------------------------------
__global__ void im2col_k(const float* __restrict__ x, __half* __restrict__ col, long total)
{
    long i = (long)blockIdx.x * blockDim.x + threadIdx.x;
    if (i >= total) return;
    int k = (int)(i % EMB);
    long m = i / EMB;
    int b = (int)(m / NPATCH), p = (int)(m % NPATCH);
    int c = k >> 8, r = k & 255, ii = r >> 4, jj = r & 15;
    int py = p / 14, px = p % 14;
    col[i] = __float2half_rn(x[(((size_t)b * 3 + c) * 224 + py * 16 + ii) * 224 + px * 16 + jj]);
}

__global__ void lat1_k(const float* __restrict__ pe, const float* __restrict__ w1,
                       const float* __restrict__ b1, const float* __restrict__ budget,
                       float* __restrict__ out)
{
    int b = blockIdx.x;
    int idx = (int)rintf(budget[b] * (float)(PE_NN - 1));
    const float* row = pe + (size_t)idx * PE_DD;
    for (int e = threadIdx.x; e < EMB; e += 256) {
        float s = b1[e];
        for (int k = 0; k < PE_DD; k++) s += row[k] * w1[(size_t)k * EMB + e];
        out[(size_t)b * EMB + e] = gelu_f(s);
    }
}

__global__ void assemble_k(const float* __restrict__ lat, const float* __restrict__ cls,
                           const float* __restrict__ pat, const float* __restrict__ pos,
                           float* __restrict__ tok, long total)
{
    long i = (long)blockIdx.x * blockDim.x + threadIdx.x;
    if (i >= total) return;
    int e = (int)(i % EMB);
    long bn = i / EMB;
    int n = (int)(bn % NTOK), b = (int)(bn / NTOK);
    float v;
    if (n == 0)      v = lat[(size_t)b * EMB + e];
    else if (n == 1) v = cls[e];
    else             v = pat[((size_t)b * NPATCH + (n - 2)) * EMB + e];
    tok[i] = v + pos[(size_t)n * EMB + e];
}

__global__ void sched_k(const float* __restrict__ tok, const float* __restrict__ sw,
                        const float* __restrict__ sb, const float* __restrict__ budget,
                        int* __restrict__ active)
{
    int b = blockIdx.x, lane = threadIdx.x;
    __shared__ float lg[NADAPT];
    if (lane < NADAPT) {
        const float* x = tok + (size_t)b * NTOK * EMB;
        float s = sb[lane];
        for (int k = 0; k < EMB; k++) s += x[k] * sw[(size_t)k * NADAPT + lane];
        lg[lane] = s;
    }
    __syncwarp();
    if (lane < NADAPT) {
        int kk = (int)ceilf(budget[b] * (float)NADAPT);
        if (kk < 1) kk = 1;
        int rank = 0;
        for (int j = 0; j < NADAPT; j++)
            if (lg[j] > lg[lane] || (lg[j] == lg[lane] && j < lane)) rank++;
        active[b * NADAPT + lane] = (rank < kk) ? 1 : 0;
    }
}

__global__ void extract_k(const float* __restrict__ tok, float* __restrict__ t, long total)
{
    long i = (long)blockIdx.x * blockDim.x + threadIdx.x;
    if (i >= total) return;
    int e = (int)(i % EMB);
    long bn = i / EMB;
    int n = (int)(bn % NT2), b = (int)(bn / NT2);
    t[i] = tok[((size_t)b * NTOK + n + 1) * EMB + e];
}

__global__ void head_k(const __half* __restrict__ cls, const float* __restrict__ w,
                       const float* __restrict__ bias, float* __restrict__ out)
{
    int b = blockIdx.x, c = threadIdx.x;
    if (c >= NCLS) return;
    const __half* x = cls + (size_t)b * EMB;
    float s = bias[c];
    for (int k = 0; k < EMB; k++) s += __half2float(x[k]) * w[(size_t)k * NCLS + c];
    out[(size_t)b * NCLS + c] = s;
}

// ---------------- host orchestration ----------------------------------------
static inline void launch_gemm(int act, bool res, bool outh,
                               const __half* A, const __half* Bt, const float* bias,
                               const float* r, float* Cf, __half* Ch, int M, int N, int K,
                               const int* gate, int gstride, int rps, int gate_rows)
{
    dim3 g(N / 128, (M + 127) / 128), blk(256);
    if (outh) {
        if (act == 1)      hgemm_k<1, false, true><<<g, blk, GEMM_SMEM_BYTES>>>(A, Bt, bias, r, Cf, Ch, M, N, K, gate, gstride, rps, gate_rows);
        else               hgemm_k<0, false, true><<<g, blk, GEMM_SMEM_BYTES>>>(A, Bt, bias, r, Cf, Ch, M, N, K, gate, gstride, rps, gate_rows);
    } else {
        if (res)           hgemm_k<0, true,  false><<<g, blk, GEMM_SMEM_BYTES>>>(A, Bt, bias, r, Cf, Ch, M, N, K, gate, gstride, rps, gate_rows);
        else               hgemm_k<0, false, false><<<g, blk, GEMM_SMEM_BYTES>>>(A, Bt, bias, r, Cf, Ch, M, N, K, gate, gstride, rps, gate_rows);
    }
}

struct Ptrs {
    float *tok, *t, *t2, *pat, *lat1, *lat3;
    __half *xn, *qkv, *att, *mlp, *col, *lat2, *cls;
    __half *wqkv, *wproj, *wfc1, *wfc2, *wlat2, *wpat;
    int   *actv;
};

// Xin: residual input (read). Xmid: post-attention buffer. Xout: final target
// written by fc2 (row-gated when gate_rows=1, emulating the where-merge).
static void run_block(const Ptrs& P, float* Xin, float* Xmid, float* Xout, int N, int l,
                      const float* ln1g, const float* ln1b, const float* qkvb,
                      const float* projb, const float* ln2g, const float* ln2b,
                      const float* fc1b, const float* fc2b,
                      const int* gate, int gstride, int gate_rows)
{
    const int M = BATCH * N;
    ln_k<<<M, 192>>>(Xin, EMB, ln1g + (size_t)l * EMB, ln1b + (size_t)l * EMB,
                     P.xn, EMB, gate, gstride, N);
    launch_gemm(0, false, true, P.xn, P.wqkv + (size_t)l * EMB * 3 * EMB,
                qkvb + (size_t)l * 3 * EMB, nullptr, nullptr, P.qkv, M, 3 * EMB, EMB,
                gate, gstride, N, 0);
    attn_k<<<BATCH * HEADS, 128, ATTN_SMEM_BYTES>>>(P.qkv, P.att, N, gate, gstride);
    launch_gemm(0, true, false, P.att, P.wproj + (size_t)l * EMB * EMB,
                projb + (size_t)l * EMB, Xin, Xmid, nullptr, M, EMB, EMB,
                gate, gstride, N, 0);
    ln_k<<<M, 192>>>(Xmid, EMB, ln2g + (size_t)l * EMB, ln2b + (size_t)l * EMB,
                     P.xn, EMB, gate, gstride, N);
    launch_gemm(1, false, true, P.xn, P.wfc1 + (size_t)l * EMB * MLPD,
                fc1b + (size_t)l * MLPD, nullptr, nullptr, P.mlp, M, MLPD, EMB,
                gate, gstride, N, 0);
    launch_gemm(0, true, false, P.mlp, P.wfc2 + (size_t)l * MLPD * EMB,
                fc2b + (size_t)l * EMB, Xmid, Xout, nullptr, M, EMB, MLPD,
                gate, gstride, N, gate_rows);
}

extern "C" void kernel_launch(void* const* d_in, const int* in_sizes, int n_in,
                              void* d_out, int out_size)
{
    const float* x        = (const float*)d_in[0];
    const float* budget   = (const float*)d_in[1];
    const float* pe_table = (const float*)d_in[2];
    const float* lat_w1   = (const float*)d_in[3];
    const float* lat_b1   = (const float*)d_in[4];
    const float* lat_ln_g = (const float*)d_in[5];
    const float* lat_ln_b = (const float*)d_in[6];
    const float* lat_w2   = (const float*)d_in[7];
    const float* lat_b2   = (const float*)d_in[8];
    const float* patch_w  = (const float*)d_in[9];
    const float* patch_b  = (const float*)d_in[10];
    const float* cls_tok  = (const float*)d_in[11];
    const float* pos_emb  = (const float*)d_in[12];
    const float* sched_w  = (const float*)d_in[13];
    const float* sched_b  = (const float*)d_in[14];
    const float* ln1_g    = (const float*)d_in[15];
    const float* ln1_b    = (const float*)d_in[16];
    const float* qkv_w    = (const float*)d_in[17];
    const float* qkv_b    = (const float*)d_in[18];
    const float* proj_w   = (const float*)d_in[19];
    const float* proj_b   = (const float*)d_in[20];
    const float* ln2_g    = (const float*)d_in[21];
    const float* ln2_b    = (const float*)d_in[22];
    const float* fc1_w    = (const float*)d_in[23];
    const float* fc1_b    = (const float*)d_in[24];
    const float* fc2_w    = (const float*)d_in[25];
    const float* fc2_b    = (const float*)d_in[26];
    const float* norm_g   = (const float*)d_in[27];
    const float* norm_b   = (const float*)d_in[28];
    const float* head_w   = (const float*)d_in[29];
    const float* head_b   = (const float*)d_in[30];
    float* out = (float*)d_out;

    Ptrs P;
    cudaGetSymbolAddress((void**)&P.tok,  g_tok);
    cudaGetSymbolAddress((void**)&P.xn,   g_xn);
    cudaGetSymbolAddress((void**)&P.qkv,  g_qkv);
    cudaGetSymbolAddress((void**)&P.att,  g_attb);
    cudaGetSymbolAddress((void**)&P.mlp,  g_mlpb);
    cudaGetSymbolAddress((void**)&P.t,    g_t);
    cudaGetSymbolAddress((void**)&P.t2,   g_t2);
    cudaGetSymbolAddress((void**)&P.col,  g_col);
    cudaGetSymbolAddress((void**)&P.pat,  g_pat);
    cudaGetSymbolAddress((void**)&P.lat1, g_lat1);
    cudaGetSymbolAddress((void**)&P.lat2, g_lat2);
    cudaGetSymbolAddress((void**)&P.lat3, g_lat3);
    cudaGetSymbolAddress((void**)&P.cls,  g_cls);
    cudaGetSymbolAddress((void**)&P.actv, g_actv);
    cudaGetSymbolAddress((void**)&P.wqkv, g_wqkv);
    cudaGetSymbolAddress((void**)&P.wproj,g_wproj);
    cudaGetSymbolAddress((void**)&P.wfc1, g_wfc1);
    cudaGetSymbolAddress((void**)&P.wfc2, g_wfc2);
    cudaGetSymbolAddress((void**)&P.wlat2,g_wlat2);
    cudaGetSymbolAddress((void**)&P.wpat, g_wpat);

    cudaFuncSetAttribute(attn_k, cudaFuncAttributeMaxDynamicSharedMemorySize, ATTN_SMEM_BYTES);
    cudaFuncSetAttribute(hgemm_k<0,false,true >, cudaFuncAttributeMaxDynamicSharedMemorySize, GEMM_SMEM_BYTES);
    cudaFuncSetAttribute(hgemm_k<1,false,true >, cudaFuncAttributeMaxDynamicSharedMemorySize, GEMM_SMEM_BYTES);
    cudaFuncSetAttribute(hgemm_k<0,true, false>, cudaFuncAttributeMaxDynamicSharedMemorySize, GEMM_SMEM_BYTES);
    cudaFuncSetAttribute(hgemm_k<0,false,false>, cudaFuncAttributeMaxDynamicSharedMemorySize, GEMM_SMEM_BYTES);

    // --- weight transposes+convert ([K,N] fp32 -> [N,K] half) ---
    {
        dim3 b32(32, 8);
        transpose_k<<<dim3(3*EMB/32, EMB/32, NLAYERS), b32>>>(qkv_w,  P.wqkv,  EMB, 3*EMB);
        transpose_k<<<dim3(EMB/32,   EMB/32, NLAYERS), b32>>>(proj_w, P.wproj, EMB, EMB);
        transpose_k<<<dim3(MLPD/32,  EMB/32, NLAYERS), b32>>>(fc1_w,  P.wfc1,  EMB, MLPD);
        transpose_k<<<dim3(EMB/32,  MLPD/32, NLAYERS), b32>>>(fc2_w,  P.wfc2,  MLPD, EMB);
        transpose_k<<<dim3(EMB/32,   EMB/32, 1),       b32>>>(lat_w2, P.wlat2, EMB, EMB);
        long pw = (long)EMB * EMB;
        cvt_k<<<(unsigned)((pw + 255) / 256), 256>>>(patch_w, P.wpat, pw);
    }

    // --- latent token ---
    lat1_k<<<BATCH, 256>>>(pe_table, lat_w1, lat_b1, budget, P.lat1);
    ln_k<<<BATCH, 192>>>(P.lat1, EMB, lat_ln_g, lat_ln_b, P.lat2, EMB, nullptr, 0, 1);
    launch_gemm(0, false, false, P.lat2, P.wlat2, lat_b2, nullptr, P.lat3, nullptr,
                BATCH, EMB, EMB, nullptr, 0, 1, 0);

    // --- patch embedding ---
    {
        long tot = (long)BATCH * NPATCH * EMB;
        im2col_k<<<(unsigned)((tot + 255) / 256), 256>>>(x, P.col, tot);
        launch_gemm(0, false, false, P.col, P.wpat, patch_b, nullptr, P.pat, nullptr,
                    BATCH * NPATCH, EMB, EMB, nullptr, 0, 1, 0);
        long ta = (long)BATCH * NTOK * EMB;
        assemble_k<<<(unsigned)((ta + 255) / 256), 256>>>(P.lat3, cls_tok, P.pat,
                                                          pos_emb, P.tok, ta);
    }

    // --- 6 fixed blocks on 198 tokens (in-place on tok) ---
    for (int l = 0; l < NFIX; l++)
        run_block(P, P.tok, P.tok, P.tok, NTOK, l, ln1_g, ln1_b, qkv_b, proj_b,
                  ln2_g, ln2_b, fc1_b, fc2_b, nullptr, 0, 0);

    // --- scheduler gating ---
    sched_k<<<BATCH, 32>>>(P.tok, sched_w, sched_b, budget, P.actv);

    // --- adaptive blocks on 197 tokens: t -> t2 (mid) -> t (gated write) ---
    const long tlen = (long)BATCH * NT2 * EMB;
    extract_k<<<(unsigned)((tlen + 255) / 256), 256>>>(P.tok, P.t, tlen);
    for (int i = 0; i < NADAPT; i++) {
        const int* gate = P.actv + i;    // gate[s * NADAPT] = active[s][i]
        run_block(P, P.t, P.t2, P.t, NT2, NFIX + i, ln1_g, ln1_b, qkv_b, proj_b,
                  ln2_g, ln2_b, fc1_b, fc2_b, gate, NADAPT, 1);
    }

    // --- final LN (only row 0 per sample needed for output) + head ---
    ln_k<<<BATCH, 192>>>(P.t, (long)NT2 * EMB, norm_g, norm_b, P.cls, EMB, nullptr, 0, 1);
    head_k<<<BATCH, 128>>>(P.cls, head_w, head_b, out);
}